// round 12
// baseline (speedup 1.0000x reference)
#include <cuda_runtime.h>
#include <cuda_bf16.h>
#include <math.h>
#include <stdint.h>

// Problem constants (fixed shapes for this problem instance)
#define NN   1024     // notes
#define LL   32768    // max note length
#define WW   1024     // hann window length
#define HH   8        // harmonics
#define KK   128      // FIR taps
#define TILE 2048     // output samples per block
#define NTHREADS 256
#define OPT  8        // outputs per thread in epilogue

#define SEG   2176    // 136 blocks of 16 samples: covers b*16+j, b<128, j<144
#define NQ    9       // k-steps of 16 (K=144 padded)
#define AFRAG (NQ * 32)   // 288 per-lane A fragments

// y_s bank swizzle: permutes bits 3-4 by higher bits; conflict-free both ways
#define SWZ(i) ((i) ^ ((((i) >> 5) & 3) << 3))

// Scratch (device globals; no allocation allowed)
__device__ float g_amps[NN * HH];   // softplus(z) * vel, per note per harmonic
__device__ float g_hann[WW];
__device__ int   g_olen[NN];
__device__ uint4 g_afh4[AFRAG];     // A fragments (Toeplitz hi), mma lane order
__device__ uint4 g_afl4[AFRAG];     // A fragments (Toeplitz lo)

// ---------------------------------------------------------------------------
// Accurate sin of an fp32 argument, |x| < ~1e5.
// k via magic-constant RN-even round (no FRND), 3-term Cody-Waite, MUFU sin.
// ---------------------------------------------------------------------------
__device__ __forceinline__ float sin_ref(float x) {
    const float INV2PI = 0.15915494309189535f;
    const float MAGIC  = 12582912.0f;                 // 1.5 * 2^23
    float k = fmaf(x, INV2PI, MAGIC) - MAGIC;         // rint-even(x/2pi)
    float r = fmaf(k, -6.28125f, x);
    r = fmaf(k, -1.9359588623046875e-3f, r);
    r = fmaf(k,  6.5168271821061e-7f,  r);
    return __sinf(r);
}

// Accurate-enough tanh, branch-free (clamp at 9: error <= 1.3e-8).
__device__ __forceinline__ float tanh_ref(float x) {
    float ax = fminf(fabsf(x), 9.0f);
    float e = __expf(2.0f * ax);
    float r = 1.0f - __fdividef(2.0f, e + 1.0f);
    return copysignf(r, x);
}

// hi/lo bf16 split: hi = truncate-to-bf16 (exact), lo = rn-bf16(x - hi)
__device__ __forceinline__ void split_bf16(float x, unsigned short& h, unsigned short& l) {
    unsigned int xb = __float_as_uint(x);
    h = (unsigned short)(xb >> 16);
    float hf = __uint_as_float(xb & 0xFFFF0000u);
    float lf = x - hf;                        // exact
    __nv_bfloat16 lb = __float2bfloat16(lf);  // rn
    l = *(unsigned short*)&lb;
}

__device__ __forceinline__ unsigned int smem_u32(const void* p) {
    unsigned int a;
    asm("{ .reg .u64 t; cvta.to.shared.u64 t, %1; cvt.u32.u64 %0, t; }"
        : "=r"(a) : "l"(p));
    return a;
}

// ---------------------------------------------------------------------------
// Prep kernel (also zeros d_out): per-note MLPs, hann table, A-fragment
// precompute (Toeplitz Fe[p][j] = fir[j-p] in exact mma lane order).
// ---------------------------------------------------------------------------
__device__ __forceinline__ float fe_val(const float* fir, int p, int j) {
    int d = j - p;
    return (d >= 0 && d < KK) ? fir[d] : 0.0f;
}

__global__ void prep_kernel(
    const float* __restrict__ freq, const float* __restrict__ velocity,
    const float* __restrict__ w1,  const float* __restrict__ b1,
    const float* __restrict__ w2,  const float* __restrict__ b2,
    const float* __restrict__ ws1, const float* __restrict__ bs1,
    const float* __restrict__ ws2, const float* __restrict__ bs2,
    const float* __restrict__ fir,
    const int*   __restrict__ starts, const int* __restrict__ lengths,
    float* __restrict__ out, int D)
{
    int i = blockIdx.x * blockDim.x + threadIdx.x;

    // zero the output (harness poisons it)
    int n4 = D >> 2;
    if (i < n4) ((float4*)out)[i] = make_float4(0.f, 0.f, 0.f, 0.f);
    int tail = n4 * 4 + i;
    if (i < 4 && tail < D) out[tail] = 0.0f;

    // A fragments: thread i = q*32 + lane computes its uint4 (hi and lo).
    // mma m16n8k16 A lane map: rr = lane>>2, kq = (lane&3)*2, ja = q*16+kq:
    //   a0=(Fe[rr][ja],Fe[rr][ja+1])  a1=(Fe[rr+8][ja],..)
    //   a2=(Fe[rr][ja+8],..)          a3=(Fe[rr+8][ja+8],..)
    if (i < AFRAG) {
        int q = i >> 5, L = i & 31;
        int rr = L >> 2, ja = q * 16 + ((L & 3) << 1);
        uint4 H, Lo;
        unsigned int* hp = &H.x;
        unsigned int* lp = &Lo.x;
        #pragma unroll
        for (int t = 0; t < 4; ++t) {
            int p = rr + ((t & 1) << 3);
            int j = ja + ((t >> 1) << 3);
            unsigned short h0, l0, h1, l1;
            split_bf16(fe_val(fir, p, j),     h0, l0);
            split_bf16(fe_val(fir, p, j + 1), h1, l1);
            hp[t] = (unsigned)h0 | ((unsigned)h1 << 16);
            lp[t] = (unsigned)l0 | ((unsigned)l1 << 16);
        }
        g_afh4[i] = H;
        g_afl4[i] = Lo;
    }

    if (i < WW) {
        // exactly replicate reference arg: fl(fl(2pi_f32 * n) / 1024)
        float a = 6.283185307179586f * (float)i * (1.0f / 1024.0f);
        double c = cos((double)a);
        g_hann[i] = 0.5f * (1.0f - (float)c);
    }

    if (i < NN) {
        int st = starts[i];
        int en = st + lengths[i];
        int ol = min(en, D) - st;
        ol = max(0, min(ol, LL));
        g_olen[i] = ol;

        // time embedder: Linear(1,32) -> ReLU -> Linear(32,2)
        float nt = (float)st / (float)D;
        float lat0 = b2[0], lat1 = b2[1];
        #pragma unroll 8
        for (int j = 0; j < 32; ++j) {
            float h = fmaxf(fmaf(nt, w1[j], b1[j]), 0.0f);
            lat0 = fmaf(h, w2[j * 2 + 0], lat0);
            lat1 = fmaf(h, w2[j * 2 + 1], lat1);
        }

        float vel = velocity[i] * (1.0f / 127.0f);
        float feat0 = freq[i], feat1 = vel;

        // synth MLP: (4 -> 64 -> 8), softplus on output
        float z[HH];
        #pragma unroll
        for (int h = 0; h < HH; ++h) z[h] = bs2[h];
        #pragma unroll 4
        for (int j = 0; j < 64; ++j) {
            float h2 = bs1[j];
            h2 = fmaf(feat0, ws1[0 * 64 + j], h2);
            h2 = fmaf(feat1, ws1[1 * 64 + j], h2);
            h2 = fmaf(lat0,  ws1[2 * 64 + j], h2);
            h2 = fmaf(lat1,  ws1[3 * 64 + j], h2);
            h2 = fmaxf(h2, 0.0f);
            #pragma unroll
            for (int h = 0; h < HH; ++h)
                z[h] = fmaf(h2, ws2[j * HH + h], z[h]);
        }
        #pragma unroll
        for (int h = 0; h < HH; ++h) {
            float zz = z[h];
            float sp = fmaxf(zz, 0.0f) + log1pf(__expf(-fabsf(zz)));
            g_amps[i * HH + h] = sp * vel;            // fold vel into amps
        }
    }
}

// ---------------------------------------------------------------------------
// Main kernel.
// Segment smem layout (conflict-free for both STS.32 writes and ldmatrix):
//   sample e: b = e>>4, k = e&15, kt = k>>3
//   group = ((b&7) ^ (kt<<2)) | (kt<<3)
//   addr_shorts = (b>>3)*128 + group*8 + (k&7)
// Every ldmatrix B tile (8 rows of 16B) then covers all 8 bank-groups.
//
// Phase 1: scalar synthesis (bit-matches ref arg quantization), 2 samples
//          per thread, packed STS.32.
// Phase 2: FIR GEMM: A fragments via coalesced LDG.128 (precomputed),
//          B via ldmatrix.x4, mma.m16n8k16 bf16, 3 split products.
// Phase 3: coalesced tanh + scalar RED.ADD scatter (y_s XOR-swizzled).
//
// jax conv is CROSS-CORRELATION with left pad (K-1):
//   y[r] = sum_{k=0..127} fir[k] * s[r + k],  s[e] = x(t0 - 127 + e)
// ---------------------------------------------------------------------------
__device__ __forceinline__ void mma_bf16(float& d0, float& d1, float& d2, float& d3,
                                         unsigned int a0, unsigned int a1,
                                         unsigned int a2, unsigned int a3,
                                         unsigned int b0, unsigned int b1) {
    asm volatile(
        "mma.sync.aligned.m16n8k16.row.col.f32.bf16.bf16.f32 "
        "{%0,%1,%2,%3}, {%4,%5,%6,%7}, {%8,%9}, {%0,%1,%2,%3};"
        : "+f"(d0), "+f"(d1), "+f"(d2), "+f"(d3)
        : "r"(a0), "r"(a1), "r"(a2), "r"(a3), "r"(b0), "r"(b1));
}

#define LDSM_X4(r0, r1, r2, r3, addr) \
    asm volatile("ldmatrix.sync.aligned.m8n8.x4.shared.b16 {%0,%1,%2,%3}, [%4];" \
        : "=r"(r0), "=r"(r1), "=r"(r2), "=r"(r3) : "r"(addr))

__global__ void __launch_bounds__(NTHREADS)
synth_kernel(const float* __restrict__ freq,
             const int*   __restrict__ starts,
             float*       __restrict__ out)
{
    const int note = blockIdx.y;
    const int olen = g_olen[note];
    const int t0   = blockIdx.x * TILE;
    if (t0 >= olen) return;                  // uniform early exit

    __shared__ __align__(16) unsigned short s_h[SEG], s_l[SEG];
    __shared__ __align__(16) float y_s[TILE];

    const int tid = threadIdx.x;

    // per-note constants (uniform loads)
    const float f0 = __ldg(&freq[note]);
    const int   start = __ldg(&starts[note]);
    float amp[HH];
    #pragma unroll
    for (int h = 0; h < HH; ++h) amp[h] = __ldg(&g_amps[note * HH + h]);

    // ---- phase 1: synthesize 2 samples/thread, packed STS.32 ----
    const int wstart = olen - WW;
    for (int p = tid; p < SEG / 2; p += NTHREADS) {
        const int e = 2 * p;
        float v01[2];
        #pragma unroll
        for (int u = 0; u < 2; ++u) {
            int t = t0 - 127 + e + u;
            float v = 0.0f;
            if ((unsigned)t < (unsigned)olen) {
                float ph = f0 * (float)t;    // matches ref fp32 phase
                float acc = 0.0f;
                #pragma unroll
                for (int h = 1; h <= HH; ++h) {
                    float arg = (float)h * ph;   // matches ref fl(h*phase)
                    acc = fmaf(amp[h - 1], sin_ref(arg), acc);
                }
                int wpos = t - wstart;
                if (wpos >= 0) acc *= g_hann[wpos];
                v = acc;
            }
            v01[u] = v;
        }
        unsigned int b0 = __float_as_uint(v01[0]);
        unsigned int b1 = __float_as_uint(v01[1]);
        unsigned int hw = __byte_perm(b0, b1, 0x7632);   // packed hi bf16 pair
        float lo0 = v01[0] - __uint_as_float(b0 & 0xFFFF0000u);
        float lo1 = v01[1] - __uint_as_float(b1 & 0xFFFF0000u);
        __nv_bfloat162 lp = __floats2bfloat162_rn(lo0, lo1);

        // segment layout address (e even -> pair stays inside one 8-short row)
        int b  = e >> 4, k = e & 15, kt = k >> 3;
        int grp = ((b & 7) ^ (kt << 2)) | (kt << 3);
        int adr = ((b >> 3) << 7) | (grp << 3) | (k & 7);
        *(unsigned int*)&s_h[adr] = hw;
        *(unsigned int*)&s_l[adr] = *(unsigned int*)&lp;
    }
    __syncthreads();

    // ---- phase 2: FIR GEMM: A via LDG.128, B via ldmatrix ----
    {
        const int lane = tid & 31;
        const int w    = tid >> 5;

        // B ldmatrix lane params: tile t = lane>>3 -> (g2 = t>>1, kt = t&1),
        // row nr = lane&7. Combined block index c = w*16 + g2*8 + nr + q.
        const int nr  = lane & 7;
        const int ktB = (lane >> 3) & 1;
        const int g2B = lane >> 4;
        const int c0  = w * 16 + g2B * 8 + nr;
        const int ktx = ktB << 2;
        const int kto = ktB << 3;
        const unsigned int shb = smem_u32(s_h);
        const unsigned int slb = smem_u32(s_l);

        float d0[2] = {0.f, 0.f}, d1[2] = {0.f, 0.f};
        float d2[2] = {0.f, 0.f}, d3[2] = {0.f, 0.f};

        #pragma unroll
        for (int q = 0; q < NQ; ++q) {
            uint4 Ah = __ldg(&g_afh4[q * 32 + lane]);   // coalesced 512B
            uint4 Al = __ldg(&g_afl4[q * 32 + lane]);

            int c = c0 + q;
            unsigned int row = ((unsigned)(c >> 3) << 8)
                             | ((unsigned)((((c & 7) ^ ktx) | kto)) << 4);
            unsigned int bh[4], bl[4];
            LDSM_X4(bh[0], bh[1], bh[2], bh[3], shb + row);
            LDSM_X4(bl[0], bl[1], bl[2], bl[3], slb + row);

            #pragma unroll
            for (int g2 = 0; g2 < 2; ++g2) {
                mma_bf16(d0[g2], d1[g2], d2[g2], d3[g2],
                         Ah.x, Ah.y, Ah.z, Ah.w, bh[2 * g2], bh[2 * g2 + 1]);  // hh
                mma_bf16(d0[g2], d1[g2], d2[g2], d3[g2],
                         Ah.x, Ah.y, Ah.z, Ah.w, bl[2 * g2], bl[2 * g2 + 1]);  // hl
                mma_bf16(d0[g2], d1[g2], d2[g2], d3[g2],
                         Al.x, Al.y, Al.z, Al.w, bh[2 * g2], bh[2 * g2 + 1]);  // lh
            }
        }
        // D frag: row p = rr (+8), col n = (lane&3)*2 (+1); y idx = (g*8+n)*16+p
        const int rr  = lane >> 2;
        const int col = (lane & 3) << 1;
        #pragma unroll
        for (int g2 = 0; g2 < 2; ++g2) {
            const int g = w * 2 + g2;
            const int base = (g * 8 + col) * 16 + rr;
            y_s[SWZ(base)]      = d0[g2];     // (p=rr,   n=col)
            y_s[SWZ(base + 16)] = d1[g2];     // (p=rr,   n=col+1)
            y_s[SWZ(base + 8)]  = d2[g2];     // (p=rr+8, n=col)
            y_s[SWZ(base + 24)] = d3[g2];     // (p=rr+8, n=col+1)
        }
    }
    __syncthreads();

    // ---- phase 3: coalesced tanh + scalar scatter-add ----
    const int limit = olen - t0;             // valid outputs: r < limit
    float* __restrict__ gbase = out + start + t0;
    #pragma unroll
    for (int m = 0; m < OPT; ++m) {
        int r = tid + NTHREADS * m;
        if (r < limit)
            atomicAdd(gbase + r, tanh_ref(y_s[SWZ(r)]));   // RED.ADD, coalesced
    }
}

// ---------------------------------------------------------------------------
// Launch: prep(+zero+A-fragments) -> synth (same stream, graph-capturable)
// ---------------------------------------------------------------------------
extern "C" void kernel_launch(void* const* d_in, const int* in_sizes, int n_in,
                              void* d_out, int out_size) {
    const float* freq     = (const float*)d_in[0];
    const float* velocity = (const float*)d_in[1];
    const float* w1       = (const float*)d_in[2];
    const float* b1       = (const float*)d_in[3];
    const float* w2       = (const float*)d_in[4];
    const float* b2       = (const float*)d_in[5];
    const float* ws1      = (const float*)d_in[6];
    const float* bs1      = (const float*)d_in[7];
    const float* ws2      = (const float*)d_in[8];
    const float* bs2      = (const float*)d_in[9];
    const float* fir      = (const float*)d_in[10];
    const int*   starts   = (const int*)d_in[11];
    const int*   lengths  = (const int*)d_in[12];
    float* out = (float*)d_out;
    const int D = out_size;                  // duration_samples == out_size

    int nblk = (D / 4 + NTHREADS - 1) / NTHREADS + 1;   // covers zeroing + prep
    prep_kernel<<<nblk, NTHREADS>>>(freq, velocity, w1, b1, w2, b2,
                                    ws1, bs1, ws2, bs2, fir,
                                    starts, lengths, out, D);
    dim3 grid(LL / TILE, NN);                // 16 x 1024 blocks, early-exit culls
    synth_kernel<<<grid, NTHREADS>>>(freq, starts, out);
}

// round 13
// speedup vs baseline: 1.0489x; 1.0489x over previous
#include <cuda_runtime.h>
#include <cuda_bf16.h>
#include <math.h>
#include <stdint.h>

// Problem constants (fixed shapes for this problem instance)
#define NN   1024     // notes
#define LL   32768    // max note length
#define WW   1024     // hann window length
#define HH   8        // harmonics
#define KK   128      // FIR taps
#define TILE 4096     // output samples per block (2 GEMM halves of 2048)
#define HALF 2048
#define NTHREADS 256
#define OPT  8        // outputs per thread per half in epilogue

#define NB16  272     // 16-sample blocks in segment (265 used, padded)
#define SEG   (NB16 * 16)   // 4352 shorts per split array
#define NQ    9       // k-steps of 16 (K=144 padded)
#define AFRAG (NQ * 32)     // 288 per-lane A fragments

// y_s bank swizzle: permutes bits 3-4 by higher bits; conflict-free both ways
#define SWZ(i) ((i) ^ ((((i) >> 5) & 3) << 3))

// Scratch (device globals; no allocation allowed)
__device__ float g_amps[NN * HH];   // softplus(z) * vel, per note per harmonic
__device__ float g_hann[WW];
__device__ int   g_olen[NN];
__device__ uint4 g_afh4[AFRAG];     // A fragments (Toeplitz hi), mma lane order
__device__ uint4 g_afl4[AFRAG];     // A fragments (Toeplitz lo)

// ---------------------------------------------------------------------------
// Accurate sin of an fp32 argument, |x| < ~1e5.
// k via magic-constant RN-even round, 2-term Cody-Waite (C2 full fp32
// precision: residual <= 5.8e-11 * k <= 7.3e-7 rad), MUFU sin.
// ---------------------------------------------------------------------------
__device__ __forceinline__ float sin_ref(float x) {
    const float INV2PI = 0.15915494309189535f;
    const float MAGIC  = 12582912.0f;                 // 1.5 * 2^23
    float k = fmaf(x, INV2PI, MAGIC) - MAGIC;         // rint-even(x/2pi)
    float r = fmaf(k, -6.28125f, x);                  // C1 products exact
    r = fmaf(k, -1.9353071795862623e-3f, r);          // C2 = rn(2pi - C1)
    return __sinf(r);
}

// Accurate-enough tanh, branch-free (clamp at 9: error <= 1.3e-8).
__device__ __forceinline__ float tanh_ref(float x) {
    float ax = fminf(fabsf(x), 9.0f);
    float e = __expf(2.0f * ax);
    float r = 1.0f - __fdividef(2.0f, e + 1.0f);
    return copysignf(r, x);
}

// hi/lo bf16 split: hi = truncate-to-bf16 (exact), lo = rn-bf16(x - hi)
__device__ __forceinline__ void split_bf16(float x, unsigned short& h, unsigned short& l) {
    unsigned int xb = __float_as_uint(x);
    h = (unsigned short)(xb >> 16);
    float hf = __uint_as_float(xb & 0xFFFF0000u);
    float lf = x - hf;                        // exact
    __nv_bfloat16 lb = __float2bfloat16(lf);  // rn
    l = *(unsigned short*)&lb;
}

__device__ __forceinline__ unsigned int smem_u32(const void* p) {
    unsigned int a;
    asm("{ .reg .u64 t; cvta.to.shared.u64 t, %1; cvt.u32.u64 %0, t; }"
        : "=r"(a) : "l"(p));
    return a;
}

// ---------------------------------------------------------------------------
// Prep kernel (also zeros d_out): per-note MLPs, hann table, A-fragment
// precompute (Toeplitz Fe[p][j] = fir[j-p] in exact mma lane order).
// ---------------------------------------------------------------------------
__device__ __forceinline__ float fe_val(const float* fir, int p, int j) {
    int d = j - p;
    return (d >= 0 && d < KK) ? fir[d] : 0.0f;
}

__global__ void prep_kernel(
    const float* __restrict__ freq, const float* __restrict__ velocity,
    const float* __restrict__ w1,  const float* __restrict__ b1,
    const float* __restrict__ w2,  const float* __restrict__ b2,
    const float* __restrict__ ws1, const float* __restrict__ bs1,
    const float* __restrict__ ws2, const float* __restrict__ bs2,
    const float* __restrict__ fir,
    const int*   __restrict__ starts, const int* __restrict__ lengths,
    float* __restrict__ out, int D)
{
    int i = blockIdx.x * blockDim.x + threadIdx.x;

    // zero the output (harness poisons it)
    int n4 = D >> 2;
    if (i < n4) ((float4*)out)[i] = make_float4(0.f, 0.f, 0.f, 0.f);
    int tail = n4 * 4 + i;
    if (i < 4 && tail < D) out[tail] = 0.0f;

    // A fragments: thread i = q*32 + lane computes its uint4 (hi and lo).
    if (i < AFRAG) {
        int q = i >> 5, L = i & 31;
        int rr = L >> 2, ja = q * 16 + ((L & 3) << 1);
        uint4 H, Lo;
        unsigned int* hp = &H.x;
        unsigned int* lp = &Lo.x;
        #pragma unroll
        for (int t = 0; t < 4; ++t) {
            int p = rr + ((t & 1) << 3);
            int j = ja + ((t >> 1) << 3);
            unsigned short h0, l0, h1, l1;
            split_bf16(fe_val(fir, p, j),     h0, l0);
            split_bf16(fe_val(fir, p, j + 1), h1, l1);
            hp[t] = (unsigned)h0 | ((unsigned)h1 << 16);
            lp[t] = (unsigned)l0 | ((unsigned)l1 << 16);
        }
        g_afh4[i] = H;
        g_afl4[i] = Lo;
    }

    if (i < WW) {
        // exactly replicate reference arg: fl(fl(2pi_f32 * n) / 1024)
        float a = 6.283185307179586f * (float)i * (1.0f / 1024.0f);
        double c = cos((double)a);
        g_hann[i] = 0.5f * (1.0f - (float)c);
    }

    if (i < NN) {
        int st = starts[i];
        int en = st + lengths[i];
        int ol = min(en, D) - st;
        ol = max(0, min(ol, LL));
        g_olen[i] = ol;

        // time embedder: Linear(1,32) -> ReLU -> Linear(32,2)
        float nt = (float)st / (float)D;
        float lat0 = b2[0], lat1 = b2[1];
        #pragma unroll 8
        for (int j = 0; j < 32; ++j) {
            float h = fmaxf(fmaf(nt, w1[j], b1[j]), 0.0f);
            lat0 = fmaf(h, w2[j * 2 + 0], lat0);
            lat1 = fmaf(h, w2[j * 2 + 1], lat1);
        }

        float vel = velocity[i] * (1.0f / 127.0f);
        float feat0 = freq[i], feat1 = vel;

        // synth MLP: (4 -> 64 -> 8), softplus on output
        float z[HH];
        #pragma unroll
        for (int h = 0; h < HH; ++h) z[h] = bs2[h];
        #pragma unroll 4
        for (int j = 0; j < 64; ++j) {
            float h2 = bs1[j];
            h2 = fmaf(feat0, ws1[0 * 64 + j], h2);
            h2 = fmaf(feat1, ws1[1 * 64 + j], h2);
            h2 = fmaf(lat0,  ws1[2 * 64 + j], h2);
            h2 = fmaf(lat1,  ws1[3 * 64 + j], h2);
            h2 = fmaxf(h2, 0.0f);
            #pragma unroll
            for (int h = 0; h < HH; ++h)
                z[h] = fmaf(h2, ws2[j * HH + h], z[h]);
        }
        #pragma unroll
        for (int h = 0; h < HH; ++h) {
            float zz = z[h];
            float sp = fmaxf(zz, 0.0f) + log1pf(__expf(-fabsf(zz)));
            g_amps[i * HH + h] = sp * vel;            // fold vel into amps
        }
    }
}

// ---------------------------------------------------------------------------
// Main kernel: one block = 4096 outputs (2 GEMM/scatter halves of 2048).
// Segment smem layout (conflict-free for STS.32 writes and ldmatrix):
//   sample e: b = e>>4, k = e&15, kt = k>>3
//   group = ((b&7) ^ (kt<<2)) | (kt<<3)
//   addr_shorts = (b>>3)*128 + group*8 + (k&7)
// Phase-1 addressing is strength-reduced: e += 512 each iter leaves b&7, k,
// kt invariant -> adr += 512, ft += 512.0f (exact).
//
// jax conv is CROSS-CORRELATION with left pad (K-1):
//   y[r] = sum_{k=0..127} fir[k] * s[r + k],  s[e] = x(t0 - 127 + e)
// ---------------------------------------------------------------------------
__device__ __forceinline__ void mma_bf16(float& d0, float& d1, float& d2, float& d3,
                                         unsigned int a0, unsigned int a1,
                                         unsigned int a2, unsigned int a3,
                                         unsigned int b0, unsigned int b1) {
    asm volatile(
        "mma.sync.aligned.m16n8k16.row.col.f32.bf16.bf16.f32 "
        "{%0,%1,%2,%3}, {%4,%5,%6,%7}, {%8,%9}, {%0,%1,%2,%3};"
        : "+f"(d0), "+f"(d1), "+f"(d2), "+f"(d3)
        : "r"(a0), "r"(a1), "r"(a2), "r"(a3), "r"(b0), "r"(b1));
}

#define LDSM_X4(r0, r1, r2, r3, addr) \
    asm volatile("ldmatrix.sync.aligned.m8n8.x4.shared.b16 {%0,%1,%2,%3}, [%4];" \
        : "=r"(r0), "=r"(r1), "=r"(r2), "=r"(r3) : "r"(addr))

__global__ void __launch_bounds__(NTHREADS)
synth_kernel(const float* __restrict__ freq,
             const int*   __restrict__ starts,
             float*       __restrict__ out)
{
    const int note = blockIdx.y;
    const int olen = g_olen[note];
    const int t0   = blockIdx.x * TILE;
    if (t0 >= olen) return;                  // uniform early exit

    __shared__ __align__(16) unsigned short s_h[SEG], s_l[SEG];
    __shared__ __align__(16) float y_s[HALF];

    const int tid = threadIdx.x;

    // per-note constants (uniform loads)
    const float f0 = __ldg(&freq[note]);
    const int   start = __ldg(&starts[note]);
    float amp[HH];
    #pragma unroll
    for (int h = 0; h < HH; ++h) amp[h] = __ldg(&g_amps[note * HH + h]);

    // ---- phase 1: synthesize 2 samples/thread/iter, packed STS.32 ----
    const int wstart = olen - WW;
    {
        int e = 2 * tid;
        int t = t0 - 127 + e;
        float ft = (float)t;                 // exact; += 512.0f per iter
        // initial packed address (invariant pattern under e += 512)
        int b  = e >> 4, k = e & 15, kt = k >> 3;
        int grp = ((b & 7) ^ (kt << 2)) | (kt << 3);
        int adr = ((b >> 3) << 7) | (grp << 3) | (k & 7);

        for (int p = tid; p < SEG / 2;
             p += NTHREADS, t += 512, ft += 512.0f, adr += 512) {
            float v01[2];
            #pragma unroll
            for (int u = 0; u < 2; ++u) {
                int tu = t + u;
                float v = 0.0f;
                if ((unsigned)tu < (unsigned)olen) {
                    float ftu = (u == 0) ? ft : (ft + 1.0f);
                    float ph = f0 * ftu;         // matches ref fp32 phase
                    float acc = 0.0f;
                    #pragma unroll
                    for (int h = 1; h <= HH; ++h) {
                        float arg = (float)h * ph;   // matches ref fl(h*phase)
                        acc = fmaf(amp[h - 1], sin_ref(arg), acc);
                    }
                    int wpos = tu - wstart;
                    if (wpos >= 0) acc *= g_hann[wpos];
                    v = acc;
                }
                v01[u] = v;
            }
            unsigned int b0 = __float_as_uint(v01[0]);
            unsigned int b1 = __float_as_uint(v01[1]);
            unsigned int hw = __byte_perm(b0, b1, 0x7632);   // hi bf16 pair
            float lo0 = v01[0] - __uint_as_float(b0 & 0xFFFF0000u);
            float lo1 = v01[1] - __uint_as_float(b1 & 0xFFFF0000u);
            __nv_bfloat162 lp = __floats2bfloat162_rn(lo0, lo1);
            *(unsigned int*)&s_h[adr] = hw;
            *(unsigned int*)&s_l[adr] = *(unsigned int*)&lp;
        }
    }
    __syncthreads();

    // ---- per half: GEMM (A via LDG.128, B via ldmatrix) + scatter ----
    const int lane = tid & 31;
    const int w    = tid >> 5;
    const int nr   = lane & 7;
    const int ktB  = (lane >> 3) & 1;
    const int g2B  = lane >> 4;
    const int ktx  = ktB << 2;
    const int kto  = ktB << 3;
    const unsigned int shb = smem_u32(s_h);
    const unsigned int slb = smem_u32(s_l);
    const int rr  = lane >> 2;
    const int col = (lane & 3) << 1;
    const int limit = olen - t0;
    float* __restrict__ gbase = out + start + t0;

    #pragma unroll
    for (int half = 0; half < 2; ++half) {
        if (half * HALF >= limit) break;     // uniform: tail half skipped

        const int c0 = half * 128 + w * 16 + g2B * 8 + nr;
        float d0[2] = {0.f, 0.f}, d1[2] = {0.f, 0.f};
        float d2[2] = {0.f, 0.f}, d3[2] = {0.f, 0.f};

        #pragma unroll
        for (int q = 0; q < NQ; ++q) {
            uint4 Ah = __ldg(&g_afh4[q * 32 + lane]);   // coalesced 512B
            uint4 Al = __ldg(&g_afl4[q * 32 + lane]);

            int c = c0 + q;
            unsigned int row = ((unsigned)(c >> 3) << 8)
                             | ((unsigned)((((c & 7) ^ ktx) | kto)) << 4);
            unsigned int bh[4], bl[4];
            LDSM_X4(bh[0], bh[1], bh[2], bh[3], shb + row);
            LDSM_X4(bl[0], bl[1], bl[2], bl[3], slb + row);

            #pragma unroll
            for (int g2 = 0; g2 < 2; ++g2) {
                mma_bf16(d0[g2], d1[g2], d2[g2], d3[g2],
                         Ah.x, Ah.y, Ah.z, Ah.w, bh[2 * g2], bh[2 * g2 + 1]); // hh
                mma_bf16(d0[g2], d1[g2], d2[g2], d3[g2],
                         Ah.x, Ah.y, Ah.z, Ah.w, bl[2 * g2], bl[2 * g2 + 1]); // hl
                mma_bf16(d0[g2], d1[g2], d2[g2], d3[g2],
                         Al.x, Al.y, Al.z, Al.w, bh[2 * g2], bh[2 * g2 + 1]); // lh
            }
        }
        // D frag: row p = rr (+8), col n; local y idx = (g*8+n)*16+p
        #pragma unroll
        for (int g2 = 0; g2 < 2; ++g2) {
            const int g = w * 2 + g2;
            const int base = (g * 8 + col) * 16 + rr;
            y_s[SWZ(base)]      = d0[g2];
            y_s[SWZ(base + 16)] = d1[g2];
            y_s[SWZ(base + 8)]  = d2[g2];
            y_s[SWZ(base + 24)] = d3[g2];
        }
        __syncthreads();

        // coalesced tanh + scalar RED.ADD scatter for this half
        const int hoff = half * HALF;
        #pragma unroll
        for (int m = 0; m < OPT; ++m) {
            int r = tid + NTHREADS * m;
            int rg = hoff + r;
            if (rg < limit)
                atomicAdd(gbase + rg, tanh_ref(y_s[SWZ(r)]));
        }
        __syncthreads();                     // y_s reused by next half
    }
}

// ---------------------------------------------------------------------------
// Launch: prep(+zero+A-fragments) -> synth (same stream, graph-capturable)
// ---------------------------------------------------------------------------
extern "C" void kernel_launch(void* const* d_in, const int* in_sizes, int n_in,
                              void* d_out, int out_size) {
    const float* freq     = (const float*)d_in[0];
    const float* velocity = (const float*)d_in[1];
    const float* w1       = (const float*)d_in[2];
    const float* b1       = (const float*)d_in[3];
    const float* w2       = (const float*)d_in[4];
    const float* b2       = (const float*)d_in[5];
    const float* ws1      = (const float*)d_in[6];
    const float* bs1      = (const float*)d_in[7];
    const float* ws2      = (const float*)d_in[8];
    const float* bs2      = (const float*)d_in[9];
    const float* fir      = (const float*)d_in[10];
    const int*   starts   = (const int*)d_in[11];
    const int*   lengths  = (const int*)d_in[12];
    float* out = (float*)d_out;
    const int D = out_size;                  // duration_samples == out_size

    int nblk = (D / 4 + NTHREADS - 1) / NTHREADS + 1;   // covers zeroing + prep
    prep_kernel<<<nblk, NTHREADS>>>(freq, velocity, w1, b1, w2, b2,
                                    ws1, bs1, ws2, bs2, fir,
                                    starts, lengths, out, D);
    dim3 grid(LL / TILE, NN);                // 8 x 1024 blocks, early-exit culls
    synth_kernel<<<grid, NTHREADS>>>(freq, starts, out);
}

// round 14
// speedup vs baseline: 1.1066x; 1.0550x over previous
#include <cuda_runtime.h>
#include <cuda_bf16.h>
#include <math.h>
#include <stdint.h>

// Problem constants (fixed shapes for this problem instance)
#define NN   1024     // notes
#define LL   32768    // max note length
#define WW   1024     // hann window length
#define HH   8        // harmonics
#define KK   128      // FIR taps
#define TILE 4096     // output samples per block (2 GEMM halves of 2048)
#define HALF 2048
#define NTHREADS 256
#define OPT  8        // outputs per thread per half in epilogue

#define NB16  272     // 16-sample blocks in segment (265 used, padded)
#define SEG   (NB16 * 16)   // 4352 shorts per split array
#define NQ    9       // k-steps of 16 (K=144 padded)
#define AFRAG (NQ * 32)     // 288 per-lane A fragments

// y_s bank swizzle: permutes bits 3-4 by higher bits; conflict-free both ways
#define SWZ(i) ((i) ^ ((((i) >> 5) & 3) << 3))

// Scratch (device globals; no allocation allowed)
__device__ float g_amps[NN * HH];   // softplus(z) * vel, per note per harmonic
__device__ float g_hann[WW];
__device__ int   g_olen[NN];
__device__ uint4 g_afh4[AFRAG];     // A fragments (Toeplitz hi), mma lane order
__device__ uint4 g_afl4[AFRAG];     // A fragments (Toeplitz lo)

// Cody-Waite constants (2-term; C2 = rn(2pi - C1), residual <= 5.8e-11*k)
#define CW_INV2PI 0.15915494309189535f
#define CW_MAGIC  12582912.0f
#define CW_C1     6.28125f
#define CW_C2     1.9353071795862623e-3f

// full reduce: r = a mod 2pi (|r| <= pi + eps)
#define REDUCE(a, r) do { \
    float _k = fmaf((a), CW_INV2PI, CW_MAGIC) - CW_MAGIC; \
    (r) = fmaf(_k, -CW_C1, (a)); \
    (r) = fmaf(_k, -CW_C2, (r)); \
} while (0)

__device__ __forceinline__ float sin_ref(float x) {
    float r; REDUCE(x, r);
    return __sinf(r);
}

// Accurate-enough tanh, branch-free (clamp at 9: error <= 1.3e-8).
__device__ __forceinline__ float tanh_ref(float x) {
    float ax = fminf(fabsf(x), 9.0f);
    float e = __expf(2.0f * ax);
    float r = 1.0f - __fdividef(2.0f, e + 1.0f);
    return copysignf(r, x);
}

// hi/lo bf16 split: hi = truncate-to-bf16 (exact), lo = rn-bf16(x - hi)
__device__ __forceinline__ void split_bf16(float x, unsigned short& h, unsigned short& l) {
    unsigned int xb = __float_as_uint(x);
    h = (unsigned short)(xb >> 16);
    float hf = __uint_as_float(xb & 0xFFFF0000u);
    float lf = x - hf;                        // exact
    __nv_bfloat16 lb = __float2bfloat16(lf);  // rn
    l = *(unsigned short*)&lb;
}

__device__ __forceinline__ unsigned int smem_u32(const void* p) {
    unsigned int a;
    asm("{ .reg .u64 t; cvta.to.shared.u64 t, %1; cvt.u32.u64 %0, t; }"
        : "=r"(a) : "l"(p));
    return a;
}

// ---------------------------------------------------------------------------
// Prep kernel (also zeros d_out): per-note MLPs, hann table, A-fragment
// precompute (Toeplitz Fe[p][j] = fir[j-p] in exact mma lane order).
// ---------------------------------------------------------------------------
__device__ __forceinline__ float fe_val(const float* fir, int p, int j) {
    int d = j - p;
    return (d >= 0 && d < KK) ? fir[d] : 0.0f;
}

__global__ void prep_kernel(
    const float* __restrict__ freq, const float* __restrict__ velocity,
    const float* __restrict__ w1,  const float* __restrict__ b1,
    const float* __restrict__ w2,  const float* __restrict__ b2,
    const float* __restrict__ ws1, const float* __restrict__ bs1,
    const float* __restrict__ ws2, const float* __restrict__ bs2,
    const float* __restrict__ fir,
    const int*   __restrict__ starts, const int* __restrict__ lengths,
    float* __restrict__ out, int D)
{
    int i = blockIdx.x * blockDim.x + threadIdx.x;

    // zero the output (harness poisons it)
    int n4 = D >> 2;
    if (i < n4) ((float4*)out)[i] = make_float4(0.f, 0.f, 0.f, 0.f);
    int tail = n4 * 4 + i;
    if (i < 4 && tail < D) out[tail] = 0.0f;

    // A fragments: thread i = q*32 + lane computes its uint4 (hi and lo).
    if (i < AFRAG) {
        int q = i >> 5, L = i & 31;
        int rr = L >> 2, ja = q * 16 + ((L & 3) << 1);
        uint4 H, Lo;
        unsigned int* hp = &H.x;
        unsigned int* lp = &Lo.x;
        #pragma unroll
        for (int t = 0; t < 4; ++t) {
            int p = rr + ((t & 1) << 3);
            int j = ja + ((t >> 1) << 3);
            unsigned short h0, l0, h1, l1;
            split_bf16(fe_val(fir, p, j),     h0, l0);
            split_bf16(fe_val(fir, p, j + 1), h1, l1);
            hp[t] = (unsigned)h0 | ((unsigned)h1 << 16);
            lp[t] = (unsigned)l0 | ((unsigned)l1 << 16);
        }
        g_afh4[i] = H;
        g_afl4[i] = Lo;
    }

    if (i < WW) {
        // exactly replicate reference arg: fl(fl(2pi_f32 * n) / 1024)
        float a = 6.283185307179586f * (float)i * (1.0f / 1024.0f);
        double c = cos((double)a);
        g_hann[i] = 0.5f * (1.0f - (float)c);
    }

    if (i < NN) {
        int st = starts[i];
        int en = st + lengths[i];
        int ol = min(en, D) - st;
        ol = max(0, min(ol, LL));
        g_olen[i] = ol;

        // time embedder: Linear(1,32) -> ReLU -> Linear(32,2)
        float nt = (float)st / (float)D;
        float lat0 = b2[0], lat1 = b2[1];
        #pragma unroll 8
        for (int j = 0; j < 32; ++j) {
            float h = fmaxf(fmaf(nt, w1[j], b1[j]), 0.0f);
            lat0 = fmaf(h, w2[j * 2 + 0], lat0);
            lat1 = fmaf(h, w2[j * 2 + 1], lat1);
        }

        float vel = velocity[i] * (1.0f / 127.0f);
        float feat0 = freq[i], feat1 = vel;

        // synth MLP: (4 -> 64 -> 8), softplus on output
        float z[HH];
        #pragma unroll
        for (int h = 0; h < HH; ++h) z[h] = bs2[h];
        #pragma unroll 4
        for (int j = 0; j < 64; ++j) {
            float h2 = bs1[j];
            h2 = fmaf(feat0, ws1[0 * 64 + j], h2);
            h2 = fmaf(feat1, ws1[1 * 64 + j], h2);
            h2 = fmaf(lat0,  ws1[2 * 64 + j], h2);
            h2 = fmaf(lat1,  ws1[3 * 64 + j], h2);
            h2 = fmaxf(h2, 0.0f);
            #pragma unroll
            for (int h = 0; h < HH; ++h)
                z[h] = fmaf(h2, ws2[j * HH + h], z[h]);
        }
        #pragma unroll
        for (int h = 0; h < HH; ++h) {
            float zz = z[h];
            float sp = fmaxf(zz, 0.0f) + log1pf(__expf(-fabsf(zz)));
            g_amps[i * HH + h] = sp * vel;            // fold vel into amps
        }
    }
}

// ---------------------------------------------------------------------------
// Main kernel: one block = 4096 outputs (2 GEMM/scatter halves of 2048).
//
// Phase-1 harmonic factorization (exact in the quantized-arg sense):
//   ref arg_h = fl(h * ph). fl(2x) = 2x exactly in fp32, so
//   arg_2 = 2*arg_1, arg_4 = 2*arg_2, arg_8 = 2*arg_4, arg_6 = 2*arg_3.
//   => sin(arg_2h) = 2 sin(arg_h) cos(arg_h): only h in {1,3,5,7} need a
//   full reduce + MUFU; h in {2,4,6,8} come from double-angle FMAs.
//
// jax conv is CROSS-CORRELATION with left pad (K-1):
//   y[r] = sum_{k=0..127} fir[k] * s[r + k],  s[e] = x(t0 - 127 + e)
// ---------------------------------------------------------------------------
__device__ __forceinline__ void mma_bf16(float& d0, float& d1, float& d2, float& d3,
                                         unsigned int a0, unsigned int a1,
                                         unsigned int a2, unsigned int a3,
                                         unsigned int b0, unsigned int b1) {
    asm volatile(
        "mma.sync.aligned.m16n8k16.row.col.f32.bf16.bf16.f32 "
        "{%0,%1,%2,%3}, {%4,%5,%6,%7}, {%8,%9}, {%0,%1,%2,%3};"
        : "+f"(d0), "+f"(d1), "+f"(d2), "+f"(d3)
        : "r"(a0), "r"(a1), "r"(a2), "r"(a3), "r"(b0), "r"(b1));
}

#define LDSM_X4(r0, r1, r2, r3, addr) \
    asm volatile("ldmatrix.sync.aligned.m8n8.x4.shared.b16 {%0,%1,%2,%3}, [%4];" \
        : "=r"(r0), "=r"(r1), "=r"(r2), "=r"(r3) : "r"(addr))

__global__ void __launch_bounds__(NTHREADS)
synth_kernel(const float* __restrict__ freq,
             const int*   __restrict__ starts,
             float*       __restrict__ out)
{
    const int note = blockIdx.y;
    const int olen = g_olen[note];
    const int t0   = blockIdx.x * TILE;
    if (t0 >= olen) return;                  // uniform early exit

    __shared__ __align__(16) unsigned short s_h[SEG], s_l[SEG];
    __shared__ __align__(16) float y_s[HALF];

    const int tid = threadIdx.x;

    // per-note constants (uniform loads)
    const float f0 = __ldg(&freq[note]);
    const int   start = __ldg(&starts[note]);
    float amp[HH];
    #pragma unroll
    for (int h = 0; h < HH; ++h) amp[h] = __ldg(&g_amps[note * HH + h]);

    // ---- phase 1: synthesize 2 samples/thread/iter, packed STS.32 ----
    const int wstart = olen - WW;
    {
        int e = 2 * tid;
        int t = t0 - 127 + e;
        float ft = (float)t;                 // exact; += 512.0f per iter
        // initial packed address (invariant pattern under e += 512)
        int b  = e >> 4, k = e & 15, kt = k >> 3;
        int grp = ((b & 7) ^ (kt << 2)) | (kt << 3);
        int adr = ((b >> 3) << 7) | (grp << 3) | (k & 7);

        for (int p = tid; p < SEG / 2;
             p += NTHREADS, t += 512, ft += 512.0f, adr += 512) {
            float v01[2];
            #pragma unroll
            for (int u = 0; u < 2; ++u) {
                int tu = t + u;
                float v = 0.0f;
                if ((unsigned)tu < (unsigned)olen) {
                    float ftu = (u == 0) ? ft : (ft + 1.0f);
                    float ph = f0 * ftu;         // = ref fl(f*t) = arg_1
                    // odd harmonics: full reduce + MUFU
                    float r1; REDUCE(ph, r1);
                    float s1 = __sinf(r1), c1 = __cosf(r1);
                    float a3 = 3.0f * ph;        // = ref fl(3*ph)
                    float r3; REDUCE(a3, r3);
                    float s3 = __sinf(r3), c3 = __cosf(r3);
                    float a5 = 5.0f * ph;
                    float r5; REDUCE(a5, r5);
                    float s5 = __sinf(r5);
                    float a7 = 7.0f * ph;
                    float r7; REDUCE(a7, r7);
                    float s7 = __sinf(r7);
                    // even harmonics by exact-arg double angle
                    float t1 = s1 * c1;  float s2 = t1 + t1;
                    float c2 = fmaf(-2.0f * s1, s1, 1.0f);
                    float t2 = s2 * c2;  float s4 = t2 + t2;
                    float c4 = fmaf(-2.0f * s2, s2, 1.0f);
                    float t4 = s4 * c4;  float s8 = t4 + t4;
                    float t3 = s3 * c3;  float s6 = t3 + t3;
                    // weighted sum
                    float acc = s1 * amp[0];
                    acc = fmaf(amp[1], s2, acc);
                    acc = fmaf(amp[2], s3, acc);
                    acc = fmaf(amp[3], s4, acc);
                    acc = fmaf(amp[4], s5, acc);
                    acc = fmaf(amp[5], s6, acc);
                    acc = fmaf(amp[6], s7, acc);
                    acc = fmaf(amp[7], s8, acc);
                    int wpos = tu - wstart;
                    if (wpos >= 0) acc *= g_hann[wpos];
                    v = acc;
                }
                v01[u] = v;
            }
            unsigned int b0 = __float_as_uint(v01[0]);
            unsigned int b1 = __float_as_uint(v01[1]);
            unsigned int hw = __byte_perm(b0, b1, 0x7632);   // hi bf16 pair
            float lo0 = v01[0] - __uint_as_float(b0 & 0xFFFF0000u);
            float lo1 = v01[1] - __uint_as_float(b1 & 0xFFFF0000u);
            __nv_bfloat162 lp = __floats2bfloat162_rn(lo0, lo1);
            *(unsigned int*)&s_h[adr] = hw;
            *(unsigned int*)&s_l[adr] = *(unsigned int*)&lp;
        }
    }
    __syncthreads();

    // ---- per half: GEMM (A via LDG.128, B via ldmatrix) + scatter ----
    const int lane = tid & 31;
    const int w    = tid >> 5;
    const int nr   = lane & 7;
    const int ktB  = (lane >> 3) & 1;
    const int g2B  = lane >> 4;
    const int ktx  = ktB << 2;
    const int kto  = ktB << 3;
    const unsigned int shb = smem_u32(s_h);
    const unsigned int slb = smem_u32(s_l);
    const int rr  = lane >> 2;
    const int col = (lane & 3) << 1;
    const int limit = olen - t0;
    float* __restrict__ gbase = out + start + t0;

    #pragma unroll
    for (int half = 0; half < 2; ++half) {
        if (half * HALF >= limit) break;     // uniform: tail half skipped

        const int c0 = half * 128 + w * 16 + g2B * 8 + nr;
        float d0[2] = {0.f, 0.f}, d1[2] = {0.f, 0.f};
        float d2[2] = {0.f, 0.f}, d3[2] = {0.f, 0.f};

        #pragma unroll
        for (int q = 0; q < NQ; ++q) {
            uint4 Ah = __ldg(&g_afh4[q * 32 + lane]);   // coalesced 512B
            uint4 Al = __ldg(&g_afl4[q * 32 + lane]);

            int c = c0 + q;
            unsigned int row = ((unsigned)(c >> 3) << 8)
                             | ((unsigned)((((c & 7) ^ ktx) | kto)) << 4);
            unsigned int bh[4], bl[4];
            LDSM_X4(bh[0], bh[1], bh[2], bh[3], shb + row);
            LDSM_X4(bl[0], bl[1], bl[2], bl[3], slb + row);

            #pragma unroll
            for (int g2 = 0; g2 < 2; ++g2) {
                mma_bf16(d0[g2], d1[g2], d2[g2], d3[g2],
                         Ah.x, Ah.y, Ah.z, Ah.w, bh[2 * g2], bh[2 * g2 + 1]); // hh
                mma_bf16(d0[g2], d1[g2], d2[g2], d3[g2],
                         Ah.x, Ah.y, Ah.z, Ah.w, bl[2 * g2], bl[2 * g2 + 1]); // hl
                mma_bf16(d0[g2], d1[g2], d2[g2], d3[g2],
                         Al.x, Al.y, Al.z, Al.w, bh[2 * g2], bh[2 * g2 + 1]); // lh
            }
        }
        // D frag: row p = rr (+8), col n; local y idx = (g*8+n)*16+p
        #pragma unroll
        for (int g2 = 0; g2 < 2; ++g2) {
            const int g = w * 2 + g2;
            const int base = (g * 8 + col) * 16 + rr;
            y_s[SWZ(base)]      = d0[g2];
            y_s[SWZ(base + 16)] = d1[g2];
            y_s[SWZ(base + 8)]  = d2[g2];
            y_s[SWZ(base + 24)] = d3[g2];
        }
        __syncthreads();

        // coalesced tanh + scalar RED.ADD scatter for this half
        const int hoff = half * HALF;
        #pragma unroll
        for (int m = 0; m < OPT; ++m) {
            int r = tid + NTHREADS * m;
            int rg = hoff + r;
            if (rg < limit)
                atomicAdd(gbase + rg, tanh_ref(y_s[SWZ(r)]));
        }
        __syncthreads();                     // y_s reused by next half
    }
}

// ---------------------------------------------------------------------------
// Launch: prep(+zero+A-fragments) -> synth (same stream, graph-capturable)
// ---------------------------------------------------------------------------
extern "C" void kernel_launch(void* const* d_in, const int* in_sizes, int n_in,
                              void* d_out, int out_size) {
    const float* freq     = (const float*)d_in[0];
    const float* velocity = (const float*)d_in[1];
    const float* w1       = (const float*)d_in[2];
    const float* b1       = (const float*)d_in[3];
    const float* w2       = (const float*)d_in[4];
    const float* b2       = (const float*)d_in[5];
    const float* ws1      = (const float*)d_in[6];
    const float* bs1      = (const float*)d_in[7];
    const float* ws2      = (const float*)d_in[8];
    const float* bs2      = (const float*)d_in[9];
    const float* fir      = (const float*)d_in[10];
    const int*   starts   = (const int*)d_in[11];
    const int*   lengths  = (const int*)d_in[12];
    float* out = (float*)d_out;
    const int D = out_size;                  // duration_samples == out_size

    int nblk = (D / 4 + NTHREADS - 1) / NTHREADS + 1;   // covers zeroing + prep
    prep_kernel<<<nblk, NTHREADS>>>(freq, velocity, w1, b1, w2, b2,
                                    ws1, bs1, ws2, bs2, fir,
                                    starts, lengths, out, D);
    dim3 grid(LL / TILE, NN);                // 8 x 1024 blocks, early-exit culls
    synth_kernel<<<grid, NTHREADS>>>(freq, starts, out);
}

// round 15
// speedup vs baseline: 1.1069x; 1.0003x over previous
#include <cuda_runtime.h>
#include <cuda_bf16.h>
#include <math.h>
#include <stdint.h>

// Problem constants (fixed shapes for this problem instance)
#define NN   1024     // notes
#define LL   32768    // max note length
#define WW   1024     // hann window length
#define HH   8        // harmonics
#define KK   128      // FIR taps
#define TILE 4096     // output samples per block (2 GEMM halves of 2048)
#define HALF 2048
#define NTHREADS 256
#define OPT  8        // outputs per thread per half in epilogue

#define NB16  272     // 16-sample blocks in segment (265 used, padded)
#define SEG   (NB16 * 16)   // 4352 shorts per split array
#define NQ    9       // k-steps of 16 (K=144 padded)
#define AFRAG (NQ * 32)     // 288 per-lane A fragments

// y_s bank swizzle: permutes bits 3-4 by higher bits; conflict-free both ways
#define SWZ(i) ((i) ^ ((((i) >> 5) & 3) << 3))

// Scratch (device globals; no allocation allowed)
__device__ float g_amps[NN * HH];   // softplus(z) * vel, per note per harmonic
__device__ float g_hann[WW];
__device__ int   g_olen[NN];
__device__ uint4 g_afh4[AFRAG];     // A fragments (Toeplitz hi), mma lane order
__device__ uint4 g_afl4[AFRAG];     // A fragments (Toeplitz lo)

// Cody-Waite constants (2-term; C2 = rn(2pi - C1), residual <= 5.8e-11*k)
#define CW_INV2PI 0.15915494309189535f
#define CW_MAGIC  12582912.0f
#define CW_C1     6.28125f
#define CW_C2     1.9353071795862623e-3f

// full reduce: r = a mod 2pi (|r| <= pi + eps)
#define REDUCE(a, r) do { \
    float _k = fmaf((a), CW_INV2PI, CW_MAGIC) - CW_MAGIC; \
    (r) = fmaf(_k, -CW_C1, (a)); \
    (r) = fmaf(_k, -CW_C2, (r)); \
} while (0)

__device__ __forceinline__ float sin_ref(float x) {
    float r; REDUCE(x, r);
    return __sinf(r);
}

// Accurate-enough tanh, branch-free (clamp at 9: error <= 1.3e-8).
__device__ __forceinline__ float tanh_ref(float x) {
    float ax = fminf(fabsf(x), 9.0f);
    float e = __expf(2.0f * ax);
    float r = 1.0f - __fdividef(2.0f, e + 1.0f);
    return copysignf(r, x);
}

// hi/lo bf16 split: hi = truncate-to-bf16 (exact), lo = rn-bf16(x - hi)
__device__ __forceinline__ void split_bf16(float x, unsigned short& h, unsigned short& l) {
    unsigned int xb = __float_as_uint(x);
    h = (unsigned short)(xb >> 16);
    float hf = __uint_as_float(xb & 0xFFFF0000u);
    float lf = x - hf;                        // exact
    __nv_bfloat16 lb = __float2bfloat16(lf);  // rn
    l = *(unsigned short*)&lb;
}

__device__ __forceinline__ unsigned int smem_u32(const void* p) {
    unsigned int a;
    asm("{ .reg .u64 t; cvta.to.shared.u64 t, %1; cvt.u32.u64 %0, t; }"
        : "=r"(a) : "l"(p));
    return a;
}

// ---------------------------------------------------------------------------
// Prep kernel (also zeros d_out): per-note MLPs, hann table, A-fragment
// precompute (Toeplitz Fe[p][j] = fir[j-p] in exact mma lane order).
// ---------------------------------------------------------------------------
__device__ __forceinline__ float fe_val(const float* fir, int p, int j) {
    int d = j - p;
    return (d >= 0 && d < KK) ? fir[d] : 0.0f;
}

__global__ void prep_kernel(
    const float* __restrict__ freq, const float* __restrict__ velocity,
    const float* __restrict__ w1,  const float* __restrict__ b1,
    const float* __restrict__ w2,  const float* __restrict__ b2,
    const float* __restrict__ ws1, const float* __restrict__ bs1,
    const float* __restrict__ ws2, const float* __restrict__ bs2,
    const float* __restrict__ fir,
    const int*   __restrict__ starts, const int* __restrict__ lengths,
    float* __restrict__ out, int D)
{
    int i = blockIdx.x * blockDim.x + threadIdx.x;

    // zero the output (harness poisons it)
    int n4 = D >> 2;
    if (i < n4) ((float4*)out)[i] = make_float4(0.f, 0.f, 0.f, 0.f);
    int tail = n4 * 4 + i;
    if (i < 4 && tail < D) out[tail] = 0.0f;

    // A fragments: thread i = q*32 + lane computes its uint4 (hi and lo).
    if (i < AFRAG) {
        int q = i >> 5, L = i & 31;
        int rr = L >> 2, ja = q * 16 + ((L & 3) << 1);
        uint4 H, Lo;
        unsigned int* hp = &H.x;
        unsigned int* lp = &Lo.x;
        #pragma unroll
        for (int t = 0; t < 4; ++t) {
            int p = rr + ((t & 1) << 3);
            int j = ja + ((t >> 1) << 3);
            unsigned short h0, l0, h1, l1;
            split_bf16(fe_val(fir, p, j),     h0, l0);
            split_bf16(fe_val(fir, p, j + 1), h1, l1);
            hp[t] = (unsigned)h0 | ((unsigned)h1 << 16);
            lp[t] = (unsigned)l0 | ((unsigned)l1 << 16);
        }
        g_afh4[i] = H;
        g_afl4[i] = Lo;
    }

    if (i < WW) {
        // exactly replicate reference arg: fl(fl(2pi_f32 * n) / 1024)
        float a = 6.283185307179586f * (float)i * (1.0f / 1024.0f);
        double c = cos((double)a);
        g_hann[i] = 0.5f * (1.0f - (float)c);
    }

    if (i < NN) {
        int st = starts[i];
        int en = st + lengths[i];
        int ol = min(en, D) - st;
        ol = max(0, min(ol, LL));
        g_olen[i] = ol;

        // time embedder: Linear(1,32) -> ReLU -> Linear(32,2)
        float nt = (float)st / (float)D;
        float lat0 = b2[0], lat1 = b2[1];
        #pragma unroll 8
        for (int j = 0; j < 32; ++j) {
            float h = fmaxf(fmaf(nt, w1[j], b1[j]), 0.0f);
            lat0 = fmaf(h, w2[j * 2 + 0], lat0);
            lat1 = fmaf(h, w2[j * 2 + 1], lat1);
        }

        float vel = velocity[i] * (1.0f / 127.0f);
        float feat0 = freq[i], feat1 = vel;

        // synth MLP: (4 -> 64 -> 8), softplus on output
        float z[HH];
        #pragma unroll
        for (int h = 0; h < HH; ++h) z[h] = bs2[h];
        #pragma unroll 4
        for (int j = 0; j < 64; ++j) {
            float h2 = bs1[j];
            h2 = fmaf(feat0, ws1[0 * 64 + j], h2);
            h2 = fmaf(feat1, ws1[1 * 64 + j], h2);
            h2 = fmaf(lat0,  ws1[2 * 64 + j], h2);
            h2 = fmaf(lat1,  ws1[3 * 64 + j], h2);
            h2 = fmaxf(h2, 0.0f);
            #pragma unroll
            for (int h = 0; h < HH; ++h)
                z[h] = fmaf(h2, ws2[j * HH + h], z[h]);
        }
        #pragma unroll
        for (int h = 0; h < HH; ++h) {
            float zz = z[h];
            float sp = fmaxf(zz, 0.0f) + log1pf(__expf(-fabsf(zz)));
            g_amps[i * HH + h] = sp * vel;            // fold vel into amps
        }
    }
}

// ---------------------------------------------------------------------------
// Main kernel: one block = 4096 outputs (2 GEMM/scatter halves of 2048).
// __launch_bounds__(256, 5): cap regs at 48 so 5 blocks (40 warps) fit per
// SM — the R14 profile showed issue 69.6% with occ 47.1% (4 blocks at 55
// regs): latency-exposed, so buy occupancy with the register slack.
//
// Phase-1 harmonic factorization (exact in the quantized-arg sense):
//   ref arg_h = fl(h * ph). fl(2x) = 2x exactly in fp32, so
//   arg_2 = 2*arg_1, arg_4 = 2*arg_2, arg_8 = 2*arg_4, arg_6 = 2*arg_3.
//   => sin(arg_2h) = 2 sin(arg_h) cos(arg_h): only h in {1,3,5,7} need a
//   full reduce + MUFU; h in {2,4,6,8} come from double-angle FMAs.
//
// jax conv is CROSS-CORRELATION with left pad (K-1):
//   y[r] = sum_{k=0..127} fir[k] * s[r + k],  s[e] = x(t0 - 127 + e)
// ---------------------------------------------------------------------------
__device__ __forceinline__ void mma_bf16(float& d0, float& d1, float& d2, float& d3,
                                         unsigned int a0, unsigned int a1,
                                         unsigned int a2, unsigned int a3,
                                         unsigned int b0, unsigned int b1) {
    asm volatile(
        "mma.sync.aligned.m16n8k16.row.col.f32.bf16.bf16.f32 "
        "{%0,%1,%2,%3}, {%4,%5,%6,%7}, {%8,%9}, {%0,%1,%2,%3};"
        : "+f"(d0), "+f"(d1), "+f"(d2), "+f"(d3)
        : "r"(a0), "r"(a1), "r"(a2), "r"(a3), "r"(b0), "r"(b1));
}

#define LDSM_X4(r0, r1, r2, r3, addr) \
    asm volatile("ldmatrix.sync.aligned.m8n8.x4.shared.b16 {%0,%1,%2,%3}, [%4];" \
        : "=r"(r0), "=r"(r1), "=r"(r2), "=r"(r3) : "r"(addr))

__global__ void __launch_bounds__(NTHREADS, 5)
synth_kernel(const float* __restrict__ freq,
             const int*   __restrict__ starts,
             float*       __restrict__ out)
{
    const int note = blockIdx.y;
    const int olen = g_olen[note];
    const int t0   = blockIdx.x * TILE;
    if (t0 >= olen) return;                  // uniform early exit

    __shared__ __align__(16) unsigned short s_h[SEG], s_l[SEG];
    __shared__ __align__(16) float y_s[HALF];

    const int tid = threadIdx.x;

    // per-note constants (uniform loads)
    const float f0 = __ldg(&freq[note]);
    const int   start = __ldg(&starts[note]);
    float amp[HH];
    #pragma unroll
    for (int h = 0; h < HH; ++h) amp[h] = __ldg(&g_amps[note * HH + h]);

    // ---- phase 1: synthesize 2 samples/thread/iter, packed STS.32 ----
    const int wstart = olen - WW;
    {
        int e = 2 * tid;
        int t = t0 - 127 + e;
        float ft = (float)t;                 // exact; += 512.0f per iter
        // initial packed address (invariant pattern under e += 512)
        int b  = e >> 4, k = e & 15, kt = k >> 3;
        int grp = ((b & 7) ^ (kt << 2)) | (kt << 3);
        int adr = ((b >> 3) << 7) | (grp << 3) | (k & 7);

        for (int p = tid; p < SEG / 2;
             p += NTHREADS, t += 512, ft += 512.0f, adr += 512) {
            float v01[2];
            #pragma unroll
            for (int u = 0; u < 2; ++u) {
                int tu = t + u;
                float v = 0.0f;
                if ((unsigned)tu < (unsigned)olen) {
                    float ftu = (u == 0) ? ft : (ft + 1.0f);
                    float ph = f0 * ftu;         // = ref fl(f*t) = arg_1
                    // odd harmonics: full reduce + MUFU
                    float r1; REDUCE(ph, r1);
                    float s1 = __sinf(r1), c1 = __cosf(r1);
                    float a3 = 3.0f * ph;        // = ref fl(3*ph)
                    float r3; REDUCE(a3, r3);
                    float s3 = __sinf(r3), c3 = __cosf(r3);
                    float a5 = 5.0f * ph;
                    float r5; REDUCE(a5, r5);
                    float s5 = __sinf(r5);
                    float a7 = 7.0f * ph;
                    float r7; REDUCE(a7, r7);
                    float s7 = __sinf(r7);
                    // even harmonics by exact-arg double angle
                    float t1 = s1 * c1;  float s2 = t1 + t1;
                    float c2 = fmaf(-2.0f * s1, s1, 1.0f);
                    float t2 = s2 * c2;  float s4 = t2 + t2;
                    float c4 = fmaf(-2.0f * s2, s2, 1.0f);
                    float t4 = s4 * c4;  float s8 = t4 + t4;
                    float t3 = s3 * c3;  float s6 = t3 + t3;
                    // weighted sum
                    float acc = s1 * amp[0];
                    acc = fmaf(amp[1], s2, acc);
                    acc = fmaf(amp[2], s3, acc);
                    acc = fmaf(amp[3], s4, acc);
                    acc = fmaf(amp[4], s5, acc);
                    acc = fmaf(amp[5], s6, acc);
                    acc = fmaf(amp[6], s7, acc);
                    acc = fmaf(amp[7], s8, acc);
                    int wpos = tu - wstart;
                    if (wpos >= 0) acc *= g_hann[wpos];
                    v = acc;
                }
                v01[u] = v;
            }
            unsigned int b0 = __float_as_uint(v01[0]);
            unsigned int b1 = __float_as_uint(v01[1]);
            unsigned int hw = __byte_perm(b0, b1, 0x7632);   // hi bf16 pair
            float lo0 = v01[0] - __uint_as_float(b0 & 0xFFFF0000u);
            float lo1 = v01[1] - __uint_as_float(b1 & 0xFFFF0000u);
            __nv_bfloat162 lp = __floats2bfloat162_rn(lo0, lo1);
            *(unsigned int*)&s_h[adr] = hw;
            *(unsigned int*)&s_l[adr] = *(unsigned int*)&lp;
        }
    }
    __syncthreads();

    // ---- per half: GEMM (A via LDG.128, B via ldmatrix) + scatter ----
    const int lane = tid & 31;
    const int w    = tid >> 5;
    const int nr   = lane & 7;
    const int ktB  = (lane >> 3) & 1;
    const int g2B  = lane >> 4;
    const int ktx  = ktB << 2;
    const int kto  = ktB << 3;
    const unsigned int shb = smem_u32(s_h);
    const unsigned int slb = smem_u32(s_l);
    const int rr  = lane >> 2;
    const int col = (lane & 3) << 1;
    const int limit = olen - t0;
    float* __restrict__ gbase = out + start + t0;

    #pragma unroll
    for (int half = 0; half < 2; ++half) {
        if (half * HALF >= limit) break;     // uniform: tail half skipped

        const int c0 = half * 128 + w * 16 + g2B * 8 + nr;
        float d0[2] = {0.f, 0.f}, d1[2] = {0.f, 0.f};
        float d2[2] = {0.f, 0.f}, d3[2] = {0.f, 0.f};

        #pragma unroll
        for (int q = 0; q < NQ; ++q) {
            uint4 Ah = __ldg(&g_afh4[q * 32 + lane]);   // coalesced 512B
            uint4 Al = __ldg(&g_afl4[q * 32 + lane]);

            int c = c0 + q;
            unsigned int row = ((unsigned)(c >> 3) << 8)
                             | ((unsigned)((((c & 7) ^ ktx) | kto)) << 4);
            unsigned int bh[4], bl[4];
            LDSM_X4(bh[0], bh[1], bh[2], bh[3], shb + row);
            LDSM_X4(bl[0], bl[1], bl[2], bl[3], slb + row);

            #pragma unroll
            for (int g2 = 0; g2 < 2; ++g2) {
                mma_bf16(d0[g2], d1[g2], d2[g2], d3[g2],
                         Ah.x, Ah.y, Ah.z, Ah.w, bh[2 * g2], bh[2 * g2 + 1]); // hh
                mma_bf16(d0[g2], d1[g2], d2[g2], d3[g2],
                         Ah.x, Ah.y, Ah.z, Ah.w, bl[2 * g2], bl[2 * g2 + 1]); // hl
                mma_bf16(d0[g2], d1[g2], d2[g2], d3[g2],
                         Al.x, Al.y, Al.z, Al.w, bh[2 * g2], bh[2 * g2 + 1]); // lh
            }
        }
        // D frag: row p = rr (+8), col n; local y idx = (g*8+n)*16+p
        #pragma unroll
        for (int g2 = 0; g2 < 2; ++g2) {
            const int g = w * 2 + g2;
            const int base = (g * 8 + col) * 16 + rr;
            y_s[SWZ(base)]      = d0[g2];
            y_s[SWZ(base + 16)] = d1[g2];
            y_s[SWZ(base + 8)]  = d2[g2];
            y_s[SWZ(base + 24)] = d3[g2];
        }
        __syncthreads();

        // coalesced tanh + scalar RED.ADD scatter for this half
        const int hoff = half * HALF;
        #pragma unroll
        for (int m = 0; m < OPT; ++m) {
            int r = tid + NTHREADS * m;
            int rg = hoff + r;
            if (rg < limit)
                atomicAdd(gbase + rg, tanh_ref(y_s[SWZ(r)]));
        }
        __syncthreads();                     // y_s reused by next half
    }
}

// ---------------------------------------------------------------------------
// Launch: prep(+zero+A-fragments) -> synth (same stream, graph-capturable)
// ---------------------------------------------------------------------------
extern "C" void kernel_launch(void* const* d_in, const int* in_sizes, int n_in,
                              void* d_out, int out_size) {
    const float* freq     = (const float*)d_in[0];
    const float* velocity = (const float*)d_in[1];
    const float* w1       = (const float*)d_in[2];
    const float* b1       = (const float*)d_in[3];
    const float* w2       = (const float*)d_in[4];
    const float* b2       = (const float*)d_in[5];
    const float* ws1      = (const float*)d_in[6];
    const float* bs1      = (const float*)d_in[7];
    const float* ws2      = (const float*)d_in[8];
    const float* bs2      = (const float*)d_in[9];
    const float* fir      = (const float*)d_in[10];
    const int*   starts   = (const int*)d_in[11];
    const int*   lengths  = (const int*)d_in[12];
    float* out = (float*)d_out;
    const int D = out_size;                  // duration_samples == out_size

    int nblk = (D / 4 + NTHREADS - 1) / NTHREADS + 1;   // covers zeroing + prep
    prep_kernel<<<nblk, NTHREADS>>>(freq, velocity, w1, b1, w2, b2,
                                    ws1, bs1, ws2, bs2, fir,
                                    starts, lengths, out, D);
    dim3 grid(LL / TILE, NN);                // 8 x 1024 blocks, early-exit culls
    synth_kernel<<<grid, NTHREADS>>>(freq, starts, out);
}

// round 16
// speedup vs baseline: 1.1401x; 1.0300x over previous
#include <cuda_runtime.h>
#include <cuda_bf16.h>
#include <math.h>
#include <stdint.h>

// Problem constants (fixed shapes for this problem instance)
#define NN   1024     // notes
#define LL   32768    // max note length
#define WW   1024     // hann window length
#define HH   8        // harmonics
#define KK   128      // FIR taps
#define TILE 4096     // output samples per block (2 GEMM halves of 2048)
#define HALF 2048
#define NTHREADS 256

#define NB16  272     // 16-sample blocks in segment (265 used, padded)
#define SEG   (NB16 * 16)   // 4352 shorts per split array
#define NQ    9       // k-steps of 16 (K=144 padded)
#define AFRAG (NQ * 32)     // 288 per-lane A fragments

// Scratch (device globals; no allocation allowed)
__device__ float g_amps[NN * HH];   // softplus(z) * vel, per note per harmonic
__device__ float g_hann[WW];
__device__ int   g_olen[NN];
__device__ uint4 g_afh4[AFRAG];     // A fragments (Toeplitz hi), mma lane order
__device__ uint4 g_afl4[AFRAG];     // A fragments (Toeplitz lo)

// Cody-Waite constants (2-term; C2 = rn(2pi - C1), residual <= 5.8e-11*k)
#define CW_INV2PI 0.15915494309189535f
#define CW_MAGIC  12582912.0f
#define CW_C1     6.28125f
#define CW_C2     1.9353071795862623e-3f

// full reduce: r = a mod 2pi (|r| <= pi + eps)
#define REDUCE(a, r) do { \
    float _k = fmaf((a), CW_INV2PI, CW_MAGIC) - CW_MAGIC; \
    (r) = fmaf(_k, -CW_C1, (a)); \
    (r) = fmaf(_k, -CW_C2, (r)); \
} while (0)

// Accurate-enough tanh, branch-free (clamp at 9: error <= 1.3e-8).
__device__ __forceinline__ float tanh_ref(float x) {
    float ax = fminf(fabsf(x), 9.0f);
    float e = __expf(2.0f * ax);
    float r = 1.0f - __fdividef(2.0f, e + 1.0f);
    return copysignf(r, x);
}

// hi/lo bf16 split: hi = truncate-to-bf16 (exact), lo = rn-bf16(x - hi)
__device__ __forceinline__ void split_bf16(float x, unsigned short& h, unsigned short& l) {
    unsigned int xb = __float_as_uint(x);
    h = (unsigned short)(xb >> 16);
    float hf = __uint_as_float(xb & 0xFFFF0000u);
    float lf = x - hf;                        // exact
    __nv_bfloat16 lb = __float2bfloat16(lf);  // rn
    l = *(unsigned short*)&lb;
}

__device__ __forceinline__ unsigned int smem_u32(const void* p) {
    unsigned int a;
    asm("{ .reg .u64 t; cvta.to.shared.u64 t, %1; cvt.u32.u64 %0, t; }"
        : "=r"(a) : "l"(p));
    return a;
}

// ---------------------------------------------------------------------------
// Prep kernel (also zeros d_out): per-note MLPs, hann table, A-fragment
// precompute (Toeplitz Fe[p][j] = fir[j-p] in exact mma lane order).
// ---------------------------------------------------------------------------
__device__ __forceinline__ float fe_val(const float* fir, int p, int j) {
    int d = j - p;
    return (d >= 0 && d < KK) ? fir[d] : 0.0f;
}

__global__ void prep_kernel(
    const float* __restrict__ freq, const float* __restrict__ velocity,
    const float* __restrict__ w1,  const float* __restrict__ b1,
    const float* __restrict__ w2,  const float* __restrict__ b2,
    const float* __restrict__ ws1, const float* __restrict__ bs1,
    const float* __restrict__ ws2, const float* __restrict__ bs2,
    const float* __restrict__ fir,
    const int*   __restrict__ starts, const int* __restrict__ lengths,
    float* __restrict__ out, int D)
{
    int i = blockIdx.x * blockDim.x + threadIdx.x;

    // zero the output (harness poisons it)
    int n4 = D >> 2;
    if (i < n4) ((float4*)out)[i] = make_float4(0.f, 0.f, 0.f, 0.f);
    int tail = n4 * 4 + i;
    if (i < 4 && tail < D) out[tail] = 0.0f;

    // A fragments: thread i = q*32 + lane computes its uint4 (hi and lo).
    if (i < AFRAG) {
        int q = i >> 5, L = i & 31;
        int rr = L >> 2, ja = q * 16 + ((L & 3) << 1);
        uint4 H, Lo;
        unsigned int* hp = &H.x;
        unsigned int* lp = &Lo.x;
        #pragma unroll
        for (int t = 0; t < 4; ++t) {
            int p = rr + ((t & 1) << 3);
            int j = ja + ((t >> 1) << 3);
            unsigned short h0, l0, h1, l1;
            split_bf16(fe_val(fir, p, j),     h0, l0);
            split_bf16(fe_val(fir, p, j + 1), h1, l1);
            hp[t] = (unsigned)h0 | ((unsigned)h1 << 16);
            lp[t] = (unsigned)l0 | ((unsigned)l1 << 16);
        }
        g_afh4[i] = H;
        g_afl4[i] = Lo;
    }

    if (i < WW) {
        // exactly replicate reference arg: fl(fl(2pi_f32 * n) / 1024)
        float a = 6.283185307179586f * (float)i * (1.0f / 1024.0f);
        double c = cos((double)a);
        g_hann[i] = 0.5f * (1.0f - (float)c);
    }

    if (i < NN) {
        int st = starts[i];
        int en = st + lengths[i];
        int ol = min(en, D) - st;
        ol = max(0, min(ol, LL));
        g_olen[i] = ol;

        // time embedder: Linear(1,32) -> ReLU -> Linear(32,2)
        float nt = (float)st / (float)D;
        float lat0 = b2[0], lat1 = b2[1];
        #pragma unroll 8
        for (int j = 0; j < 32; ++j) {
            float h = fmaxf(fmaf(nt, w1[j], b1[j]), 0.0f);
            lat0 = fmaf(h, w2[j * 2 + 0], lat0);
            lat1 = fmaf(h, w2[j * 2 + 1], lat1);
        }

        float vel = velocity[i] * (1.0f / 127.0f);
        float feat0 = freq[i], feat1 = vel;

        // synth MLP: (4 -> 64 -> 8), softplus on output
        float z[HH];
        #pragma unroll
        for (int h = 0; h < HH; ++h) z[h] = bs2[h];
        #pragma unroll 4
        for (int j = 0; j < 64; ++j) {
            float h2 = bs1[j];
            h2 = fmaf(feat0, ws1[0 * 64 + j], h2);
            h2 = fmaf(feat1, ws1[1 * 64 + j], h2);
            h2 = fmaf(lat0,  ws1[2 * 64 + j], h2);
            h2 = fmaf(lat1,  ws1[3 * 64 + j], h2);
            h2 = fmaxf(h2, 0.0f);
            #pragma unroll
            for (int h = 0; h < HH; ++h)
                z[h] = fmaf(h2, ws2[j * HH + h], z[h]);
        }
        #pragma unroll
        for (int h = 0; h < HH; ++h) {
            float zz = z[h];
            float sp = fmaxf(zz, 0.0f) + log1pf(__expf(-fabsf(zz)));
            g_amps[i * HH + h] = sp * vel;            // fold vel into amps
        }
    }
}

// ---------------------------------------------------------------------------
// Main kernel: one block = 4096 outputs (2 GEMM halves of 2048).
// SINGLE barrier per block: phase-1 writes s_h/s_l, sync, then GEMM +
// fused tanh/RED epilogue straight from mma D fragments (no y_s staging).
// D-frag map: lane (rr = lane>>2, col = (lane&3)*2), group g = w*2+g2 ->
// output words g*128 + col*16 + rr + {0,16,8,24} for d0,d1,d2,d3.
// Each warp-RED covers 4x32B sectors (same as a fully coalesced RED).
//
// Phase-1 harmonic factorization (exact in the quantized-arg sense):
//   ref arg_h = fl(h*ph); fl(2x) = 2x exactly -> sin(arg_2h) via double
//   angle from sin/cos(arg_h); only h in {1,3,5,7} need reduce + MUFU.
//
// jax conv is CROSS-CORRELATION with left pad (K-1):
//   y[r] = sum_{k=0..127} fir[k] * s[r + k],  s[e] = x(t0 - 127 + e)
// ---------------------------------------------------------------------------
__device__ __forceinline__ void mma_bf16(float& d0, float& d1, float& d2, float& d3,
                                         unsigned int a0, unsigned int a1,
                                         unsigned int a2, unsigned int a3,
                                         unsigned int b0, unsigned int b1) {
    asm volatile(
        "mma.sync.aligned.m16n8k16.row.col.f32.bf16.bf16.f32 "
        "{%0,%1,%2,%3}, {%4,%5,%6,%7}, {%8,%9}, {%0,%1,%2,%3};"
        : "+f"(d0), "+f"(d1), "+f"(d2), "+f"(d3)
        : "r"(a0), "r"(a1), "r"(a2), "r"(a3), "r"(b0), "r"(b1));
}

#define LDSM_X4(r0, r1, r2, r3, addr) \
    asm volatile("ldmatrix.sync.aligned.m8n8.x4.shared.b16 {%0,%1,%2,%3}, [%4];" \
        : "=r"(r0), "=r"(r1), "=r"(r2), "=r"(r3) : "r"(addr))

__global__ void __launch_bounds__(NTHREADS, 5)
synth_kernel(const float* __restrict__ freq,
             const int*   __restrict__ starts,
             float*       __restrict__ out)
{
    const int note = blockIdx.y;
    const int olen = g_olen[note];
    const int t0   = blockIdx.x * TILE;
    if (t0 >= olen) return;                  // uniform early exit

    __shared__ __align__(16) unsigned short s_h[SEG], s_l[SEG];

    const int tid = threadIdx.x;

    // per-note constants (uniform loads)
    const float f0 = __ldg(&freq[note]);
    const int   start = __ldg(&starts[note]);
    float amp[HH];
    #pragma unroll
    for (int h = 0; h < HH; ++h) amp[h] = __ldg(&g_amps[note * HH + h]);

    // ---- phase 1: synthesize 2 samples/thread/iter, packed STS.32 ----
    const int wstart = olen - WW;
    {
        int e = 2 * tid;
        int t = t0 - 127 + e;
        float ft = (float)t;                 // exact; += 512.0f per iter
        // initial packed address (invariant pattern under e += 512)
        int b  = e >> 4, k = e & 15, kt = k >> 3;
        int grp = ((b & 7) ^ (kt << 2)) | (kt << 3);
        int adr = ((b >> 3) << 7) | (grp << 3) | (k & 7);

        for (int p = tid; p < SEG / 2;
             p += NTHREADS, t += 512, ft += 512.0f, adr += 512) {
            float v01[2];
            #pragma unroll
            for (int u = 0; u < 2; ++u) {
                int tu = t + u;
                float v = 0.0f;
                if ((unsigned)tu < (unsigned)olen) {
                    float ftu = (u == 0) ? ft : (ft + 1.0f);
                    float ph = f0 * ftu;         // = ref fl(f*t) = arg_1
                    // odd harmonics: full reduce + MUFU
                    float r1; REDUCE(ph, r1);
                    float s1 = __sinf(r1), c1 = __cosf(r1);
                    float a3 = 3.0f * ph;        // = ref fl(3*ph)
                    float r3; REDUCE(a3, r3);
                    float s3 = __sinf(r3), c3 = __cosf(r3);
                    float a5 = 5.0f * ph;
                    float r5; REDUCE(a5, r5);
                    float s5 = __sinf(r5);
                    float a7 = 7.0f * ph;
                    float r7; REDUCE(a7, r7);
                    float s7 = __sinf(r7);
                    // even harmonics by exact-arg double angle
                    float t1 = s1 * c1;  float s2 = t1 + t1;
                    float c2 = fmaf(-2.0f * s1, s1, 1.0f);
                    float t2 = s2 * c2;  float s4 = t2 + t2;
                    float c4 = fmaf(-2.0f * s2, s2, 1.0f);
                    float t4 = s4 * c4;  float s8 = t4 + t4;
                    float t3 = s3 * c3;  float s6 = t3 + t3;
                    // weighted sum
                    float acc = s1 * amp[0];
                    acc = fmaf(amp[1], s2, acc);
                    acc = fmaf(amp[2], s3, acc);
                    acc = fmaf(amp[3], s4, acc);
                    acc = fmaf(amp[4], s5, acc);
                    acc = fmaf(amp[5], s6, acc);
                    acc = fmaf(amp[6], s7, acc);
                    acc = fmaf(amp[7], s8, acc);
                    int wpos = tu - wstart;
                    if (wpos >= 0) acc *= g_hann[wpos];
                    v = acc;
                }
                v01[u] = v;
            }
            unsigned int b0 = __float_as_uint(v01[0]);
            unsigned int b1 = __float_as_uint(v01[1]);
            unsigned int hw = __byte_perm(b0, b1, 0x7632);   // hi bf16 pair
            float lo0 = v01[0] - __uint_as_float(b0 & 0xFFFF0000u);
            float lo1 = v01[1] - __uint_as_float(b1 & 0xFFFF0000u);
            __nv_bfloat162 lp = __floats2bfloat162_rn(lo0, lo1);
            *(unsigned int*)&s_h[adr] = hw;
            *(unsigned int*)&s_l[adr] = *(unsigned int*)&lp;
        }
    }
    __syncthreads();                         // the ONLY barrier

    // ---- per half: GEMM (A via LDG.128, B via ldmatrix) + fused scatter ----
    const int lane = tid & 31;
    const int w    = tid >> 5;
    const int nr   = lane & 7;
    const int ktB  = (lane >> 3) & 1;
    const int g2B  = lane >> 4;
    const int ktx  = ktB << 2;
    const int kto  = ktB << 3;
    const unsigned int shb = smem_u32(s_h);
    const unsigned int slb = smem_u32(s_l);
    const int rr  = lane >> 2;
    const int col = (lane & 3) << 1;
    const int limit = olen - t0;
    float* __restrict__ gbase = out + start + t0;

    #pragma unroll
    for (int half = 0; half < 2; ++half) {
        if (half * HALF >= limit) break;     // uniform: tail half skipped

        const int c0 = half * 128 + w * 16 + g2B * 8 + nr;
        float d0[2] = {0.f, 0.f}, d1[2] = {0.f, 0.f};
        float d2[2] = {0.f, 0.f}, d3[2] = {0.f, 0.f};

        #pragma unroll
        for (int q = 0; q < NQ; ++q) {
            uint4 Ah = __ldg(&g_afh4[q * 32 + lane]);   // coalesced, L1-hot
            uint4 Al = __ldg(&g_afl4[q * 32 + lane]);

            int c = c0 + q;
            unsigned int row = ((unsigned)(c >> 3) << 8)
                             | ((unsigned)((((c & 7) ^ ktx) | kto)) << 4);
            unsigned int bh[4], bl[4];
            LDSM_X4(bh[0], bh[1], bh[2], bh[3], shb + row);
            LDSM_X4(bl[0], bl[1], bl[2], bl[3], slb + row);

            #pragma unroll
            for (int g2 = 0; g2 < 2; ++g2) {
                mma_bf16(d0[g2], d1[g2], d2[g2], d3[g2],
                         Ah.x, Ah.y, Ah.z, Ah.w, bh[2 * g2], bh[2 * g2 + 1]); // hh
                mma_bf16(d0[g2], d1[g2], d2[g2], d3[g2],
                         Ah.x, Ah.y, Ah.z, Ah.w, bl[2 * g2], bl[2 * g2 + 1]); // hl
                mma_bf16(d0[g2], d1[g2], d2[g2], d3[g2],
                         Al.x, Al.y, Al.z, Al.w, bh[2 * g2], bh[2 * g2 + 1]); // lh
            }
        }
        // fused epilogue: tanh + RED.ADD straight from D fragments
        const int hoff = half * HALF;
        #pragma unroll
        for (int g2 = 0; g2 < 2; ++g2) {
            const int g = w * 2 + g2;
            const int base = hoff + g * 128 + col * 16 + rr;
            if (base      < limit) atomicAdd(gbase + base,      tanh_ref(d0[g2]));
            if (base + 16 < limit) atomicAdd(gbase + base + 16, tanh_ref(d1[g2]));
            if (base + 8  < limit) atomicAdd(gbase + base + 8,  tanh_ref(d2[g2]));
            if (base + 24 < limit) atomicAdd(gbase + base + 24, tanh_ref(d3[g2]));
        }
    }
}

// ---------------------------------------------------------------------------
// Launch: prep(+zero+A-fragments) -> synth (same stream, graph-capturable)
// ---------------------------------------------------------------------------
extern "C" void kernel_launch(void* const* d_in, const int* in_sizes, int n_in,
                              void* d_out, int out_size) {
    const float* freq     = (const float*)d_in[0];
    const float* velocity = (const float*)d_in[1];
    const float* w1       = (const float*)d_in[2];
    const float* b1       = (const float*)d_in[3];
    const float* w2       = (const float*)d_in[4];
    const float* b2       = (const float*)d_in[5];
    const float* ws1      = (const float*)d_in[6];
    const float* bs1      = (const float*)d_in[7];
    const float* ws2      = (const float*)d_in[8];
    const float* bs2      = (const float*)d_in[9];
    const float* fir      = (const float*)d_in[10];
    const int*   starts   = (const int*)d_in[11];
    const int*   lengths  = (const int*)d_in[12];
    float* out = (float*)d_out;
    const int D = out_size;                  // duration_samples == out_size

    int nblk = (D / 4 + NTHREADS - 1) / NTHREADS + 1;   // covers zeroing + prep
    prep_kernel<<<nblk, NTHREADS>>>(freq, velocity, w1, b1, w2, b2,
                                    ws1, bs1, ws2, bs2, fir,
                                    starts, lengths, out, D);
    dim3 grid(LL / TILE, NN);                // 8 x 1024 blocks, early-exit culls
    synth_kernel<<<grid, NTHREADS>>>(freq, starts, out);
}

// round 17
// speedup vs baseline: 1.1767x; 1.0322x over previous
#include <cuda_runtime.h>
#include <cuda_bf16.h>
#include <math.h>
#include <stdint.h>

// Problem constants (fixed shapes for this problem instance)
#define NN   1024     // notes
#define LL   32768    // max note length
#define WW   1024     // hann window length
#define HH   8        // harmonics
#define KK   128      // FIR taps
#define TILE 4096     // output samples per block (2 GEMM halves of 2048)
#define HALF 2048
#define NTHREADS 256

#define NB16  272     // 16-sample blocks in segment (265 used, padded)
#define SEG   (NB16 * 16)   // 4352 shorts per split array
#define NQ    9       // k-steps of 16 (K=144 padded)
#define AFRAG (NQ * 32)     // 288 per-lane A fragments

// Scratch (device globals; no allocation allowed)
__device__ float g_amps[NN * HH];   // softplus(z) * vel, per note per harmonic
__device__ float g_hann[WW];
__device__ int   g_olen[NN];
__device__ uint4 g_afh4[AFRAG];     // A fragments (Toeplitz hi), mma lane order
__device__ uint4 g_afl4[AFRAG];     // A fragments (Toeplitz lo)

// Cody-Waite constants (2-term; C2 = rn(2pi - C1), residual <= 5.8e-11*k)
#define CW_INV2PI 0.15915494309189535f
#define CW_MAGIC  12582912.0f
#define CW_C1     6.28125f
#define CW_C2     1.9353071795862623e-3f

// full reduce: r = a mod 2pi (|r| <= pi + eps)
#define REDUCE(a, r) do { \
    float _k = fmaf((a), CW_INV2PI, CW_MAGIC) - CW_MAGIC; \
    (r) = fmaf(_k, -CW_C1, (a)); \
    (r) = fmaf(_k, -CW_C2, (r)); \
} while (0)

// HW tanh: max relative error ~2^-11 (4.9e-4) — bounded under the 1e-3
// threshold even if fully correlated across elements.
__device__ __forceinline__ float tanh_fast(float x) {
    float y;
    asm("tanh.approx.f32 %0, %1;" : "=f"(y) : "f"(x));
    return y;
}

// Accurate tanh for prep-side use (not perf-critical)
__device__ __forceinline__ float tanh_ref(float x) {
    float ax = fminf(fabsf(x), 9.0f);
    float e = __expf(2.0f * ax);
    float r = 1.0f - __fdividef(2.0f, e + 1.0f);
    return copysignf(r, x);
}

// hi/lo bf16 split: hi = truncate-to-bf16 (exact), lo = rn-bf16(x - hi)
__device__ __forceinline__ void split_bf16(float x, unsigned short& h, unsigned short& l) {
    unsigned int xb = __float_as_uint(x);
    h = (unsigned short)(xb >> 16);
    float hf = __uint_as_float(xb & 0xFFFF0000u);
    float lf = x - hf;                        // exact
    __nv_bfloat16 lb = __float2bfloat16(lf);  // rn
    l = *(unsigned short*)&lb;
}

__device__ __forceinline__ unsigned int smem_u32(const void* p) {
    unsigned int a;
    asm("{ .reg .u64 t; cvta.to.shared.u64 t, %1; cvt.u32.u64 %0, t; }"
        : "=r"(a) : "l"(p));
    return a;
}

// ---------------------------------------------------------------------------
// Prep kernel (output zeroing now done by a memset node): per-note MLPs,
// hann table, A-fragment precompute (Toeplitz Fe[p][j] = fir[j-p] in exact
// mma lane order). Grid: 4 blocks x 256 threads.
// ---------------------------------------------------------------------------
__device__ __forceinline__ float fe_val(const float* fir, int p, int j) {
    int d = j - p;
    return (d >= 0 && d < KK) ? fir[d] : 0.0f;
}

__global__ void prep_kernel(
    const float* __restrict__ freq, const float* __restrict__ velocity,
    const float* __restrict__ w1,  const float* __restrict__ b1,
    const float* __restrict__ w2,  const float* __restrict__ b2,
    const float* __restrict__ ws1, const float* __restrict__ bs1,
    const float* __restrict__ ws2, const float* __restrict__ bs2,
    const float* __restrict__ fir,
    const int*   __restrict__ starts, const int* __restrict__ lengths,
    int D)
{
    int i = blockIdx.x * blockDim.x + threadIdx.x;

    // A fragments: thread i = q*32 + lane computes its uint4 (hi and lo).
    if (i < AFRAG) {
        int q = i >> 5, L = i & 31;
        int rr = L >> 2, ja = q * 16 + ((L & 3) << 1);
        uint4 H, Lo;
        unsigned int* hp = &H.x;
        unsigned int* lp = &Lo.x;
        #pragma unroll
        for (int t = 0; t < 4; ++t) {
            int p = rr + ((t & 1) << 3);
            int j = ja + ((t >> 1) << 3);
            unsigned short h0, l0, h1, l1;
            split_bf16(fe_val(fir, p, j),     h0, l0);
            split_bf16(fe_val(fir, p, j + 1), h1, l1);
            hp[t] = (unsigned)h0 | ((unsigned)h1 << 16);
            lp[t] = (unsigned)l0 | ((unsigned)l1 << 16);
        }
        g_afh4[i] = H;
        g_afl4[i] = Lo;
    }

    if (i < WW) {
        // exactly replicate reference arg: fl(fl(2pi_f32 * n) / 1024)
        float a = 6.283185307179586f * (float)i * (1.0f / 1024.0f);
        double c = cos((double)a);
        g_hann[i] = 0.5f * (1.0f - (float)c);
    }

    if (i < NN) {
        int st = starts[i];
        int en = st + lengths[i];
        int ol = min(en, D) - st;
        ol = max(0, min(ol, LL));
        g_olen[i] = ol;

        // time embedder: Linear(1,32) -> ReLU -> Linear(32,2)
        float nt = (float)st / (float)D;
        float lat0 = b2[0], lat1 = b2[1];
        #pragma unroll 8
        for (int j = 0; j < 32; ++j) {
            float h = fmaxf(fmaf(nt, w1[j], b1[j]), 0.0f);
            lat0 = fmaf(h, w2[j * 2 + 0], lat0);
            lat1 = fmaf(h, w2[j * 2 + 1], lat1);
        }

        float vel = velocity[i] * (1.0f / 127.0f);
        float feat0 = freq[i], feat1 = vel;

        // synth MLP: (4 -> 64 -> 8), softplus on output
        float z[HH];
        #pragma unroll
        for (int h = 0; h < HH; ++h) z[h] = bs2[h];
        #pragma unroll 4
        for (int j = 0; j < 64; ++j) {
            float h2 = bs1[j];
            h2 = fmaf(feat0, ws1[0 * 64 + j], h2);
            h2 = fmaf(feat1, ws1[1 * 64 + j], h2);
            h2 = fmaf(lat0,  ws1[2 * 64 + j], h2);
            h2 = fmaf(lat1,  ws1[3 * 64 + j], h2);
            h2 = fmaxf(h2, 0.0f);
            #pragma unroll
            for (int h = 0; h < HH; ++h)
                z[h] = fmaf(h2, ws2[j * HH + h], z[h]);
        }
        #pragma unroll
        for (int h = 0; h < HH; ++h) {
            float zz = z[h];
            float sp = fmaxf(zz, 0.0f) + log1pf(__expf(-fabsf(zz)));
            g_amps[i * HH + h] = sp * vel;            // fold vel into amps
        }
    }
}

// ---------------------------------------------------------------------------
// Main kernel: one block = 4096 outputs (2 GEMM halves of 2048).
// SINGLE barrier per block: phase-1 writes s_h/s_l, sync, then GEMM +
// fused tanh/RED epilogue straight from mma D fragments (no y_s staging).
// D-frag map: lane (rr = lane>>2, col = (lane&3)*2), group g = w*2+g2 ->
// output words g*128 + col*16 + rr + {0,16,8,24} for d0,d1,d2,d3.
//
// Phase-1 harmonic factorization (exact in the quantized-arg sense):
//   ref arg_h = fl(h*ph); fl(2x) = 2x exactly -> sin(arg_2h) via double
//   angle from sin/cos(arg_h); only h in {1,3,5,7} need reduce + MUFU.
//
// jax conv is CROSS-CORRELATION with left pad (K-1):
//   y[r] = sum_{k=0..127} fir[k] * s[r + k],  s[e] = x(t0 - 127 + e)
// ---------------------------------------------------------------------------
__device__ __forceinline__ void mma_bf16(float& d0, float& d1, float& d2, float& d3,
                                         unsigned int a0, unsigned int a1,
                                         unsigned int a2, unsigned int a3,
                                         unsigned int b0, unsigned int b1) {
    asm volatile(
        "mma.sync.aligned.m16n8k16.row.col.f32.bf16.bf16.f32 "
        "{%0,%1,%2,%3}, {%4,%5,%6,%7}, {%8,%9}, {%0,%1,%2,%3};"
        : "+f"(d0), "+f"(d1), "+f"(d2), "+f"(d3)
        : "r"(a0), "r"(a1), "r"(a2), "r"(a3), "r"(b0), "r"(b1));
}

#define LDSM_X4(r0, r1, r2, r3, addr) \
    asm volatile("ldmatrix.sync.aligned.m8n8.x4.shared.b16 {%0,%1,%2,%3}, [%4];" \
        : "=r"(r0), "=r"(r1), "=r"(r2), "=r"(r3) : "r"(addr))

__global__ void __launch_bounds__(NTHREADS, 5)
synth_kernel(const float* __restrict__ freq,
             const int*   __restrict__ starts,
             float*       __restrict__ out)
{
    const int note = blockIdx.y;
    const int olen = g_olen[note];
    const int t0   = blockIdx.x * TILE;
    if (t0 >= olen) return;                  // uniform early exit

    __shared__ __align__(16) unsigned short s_h[SEG], s_l[SEG];

    const int tid = threadIdx.x;

    // per-note constants (uniform loads)
    const float f0 = __ldg(&freq[note]);
    const int   start = __ldg(&starts[note]);
    float amp[HH];
    #pragma unroll
    for (int h = 0; h < HH; ++h) amp[h] = __ldg(&g_amps[note * HH + h]);

    // ---- phase 1: synthesize 2 samples/thread/iter, packed STS.32 ----
    const int wstart = olen - WW;
    {
        int e = 2 * tid;
        int t = t0 - 127 + e;
        float ft = (float)t;                 // exact; += 512.0f per iter
        // initial packed address (invariant pattern under e += 512)
        int b  = e >> 4, k = e & 15, kt = k >> 3;
        int grp = ((b & 7) ^ (kt << 2)) | (kt << 3);
        int adr = ((b >> 3) << 7) | (grp << 3) | (k & 7);

        for (int p = tid; p < SEG / 2;
             p += NTHREADS, t += 512, ft += 512.0f, adr += 512) {
            float v01[2];
            #pragma unroll
            for (int u = 0; u < 2; ++u) {
                int tu = t + u;
                float v = 0.0f;
                if ((unsigned)tu < (unsigned)olen) {
                    float ftu = (u == 0) ? ft : (ft + 1.0f);
                    float ph = f0 * ftu;         // = ref fl(f*t) = arg_1
                    // odd harmonics: full reduce + MUFU
                    float r1; REDUCE(ph, r1);
                    float s1 = __sinf(r1), c1 = __cosf(r1);
                    float a3 = 3.0f * ph;        // = ref fl(3*ph)
                    float r3; REDUCE(a3, r3);
                    float s3 = __sinf(r3), c3 = __cosf(r3);
                    float a5 = 5.0f * ph;
                    float r5; REDUCE(a5, r5);
                    float s5 = __sinf(r5);
                    float a7 = 7.0f * ph;
                    float r7; REDUCE(a7, r7);
                    float s7 = __sinf(r7);
                    // even harmonics by exact-arg double angle
                    float t1 = s1 * c1;  float s2 = t1 + t1;
                    float c2 = fmaf(-2.0f * s1, s1, 1.0f);
                    float t2 = s2 * c2;  float s4 = t2 + t2;
                    float c4 = fmaf(-2.0f * s2, s2, 1.0f);
                    float t4 = s4 * c4;  float s8 = t4 + t4;
                    float t3 = s3 * c3;  float s6 = t3 + t3;
                    // weighted sum
                    float acc = s1 * amp[0];
                    acc = fmaf(amp[1], s2, acc);
                    acc = fmaf(amp[2], s3, acc);
                    acc = fmaf(amp[3], s4, acc);
                    acc = fmaf(amp[4], s5, acc);
                    acc = fmaf(amp[5], s6, acc);
                    acc = fmaf(amp[6], s7, acc);
                    acc = fmaf(amp[7], s8, acc);
                    int wpos = tu - wstart;
                    if (wpos >= 0) acc *= g_hann[wpos];
                    v = acc;
                }
                v01[u] = v;
            }
            unsigned int b0 = __float_as_uint(v01[0]);
            unsigned int b1 = __float_as_uint(v01[1]);
            unsigned int hw = __byte_perm(b0, b1, 0x7632);   // hi bf16 pair
            float lo0 = v01[0] - __uint_as_float(b0 & 0xFFFF0000u);
            float lo1 = v01[1] - __uint_as_float(b1 & 0xFFFF0000u);
            __nv_bfloat162 lp = __floats2bfloat162_rn(lo0, lo1);
            *(unsigned int*)&s_h[adr] = hw;
            *(unsigned int*)&s_l[adr] = *(unsigned int*)&lp;
        }
    }
    __syncthreads();                         // the ONLY barrier

    // ---- per half: GEMM (A via LDG.128, B via ldmatrix) + fused scatter ----
    const int lane = tid & 31;
    const int w    = tid >> 5;
    const int nr   = lane & 7;
    const int ktB  = (lane >> 3) & 1;
    const int g2B  = lane >> 4;
    const int ktx  = ktB << 2;
    const int kto  = ktB << 3;
    const unsigned int shb = smem_u32(s_h);
    const unsigned int slb = smem_u32(s_l);
    const int rr  = lane >> 2;
    const int col = (lane & 3) << 1;
    const int limit = olen - t0;
    float* __restrict__ gbase = out + start + t0;

    #pragma unroll
    for (int half = 0; half < 2; ++half) {
        if (half * HALF >= limit) break;     // uniform: tail half skipped

        const int c0 = half * 128 + w * 16 + g2B * 8 + nr;
        float d0[2] = {0.f, 0.f}, d1[2] = {0.f, 0.f};
        float d2[2] = {0.f, 0.f}, d3[2] = {0.f, 0.f};

        #pragma unroll
        for (int q = 0; q < NQ; ++q) {
            uint4 Ah = __ldg(&g_afh4[q * 32 + lane]);   // coalesced, L1-hot
            uint4 Al = __ldg(&g_afl4[q * 32 + lane]);

            int c = c0 + q;
            unsigned int row = ((unsigned)(c >> 3) << 8)
                             | ((unsigned)((((c & 7) ^ ktx) | kto)) << 4);
            unsigned int bh[4], bl[4];
            LDSM_X4(bh[0], bh[1], bh[2], bh[3], shb + row);
            LDSM_X4(bl[0], bl[1], bl[2], bl[3], slb + row);

            #pragma unroll
            for (int g2 = 0; g2 < 2; ++g2) {
                mma_bf16(d0[g2], d1[g2], d2[g2], d3[g2],
                         Ah.x, Ah.y, Ah.z, Ah.w, bh[2 * g2], bh[2 * g2 + 1]); // hh
                mma_bf16(d0[g2], d1[g2], d2[g2], d3[g2],
                         Ah.x, Ah.y, Ah.z, Ah.w, bl[2 * g2], bl[2 * g2 + 1]); // hl
                mma_bf16(d0[g2], d1[g2], d2[g2], d3[g2],
                         Al.x, Al.y, Al.z, Al.w, bh[2 * g2], bh[2 * g2 + 1]); // lh
            }
        }
        // fused epilogue: tanh + RED.ADD straight from D fragments
        const int hoff = half * HALF;
        #pragma unroll
        for (int g2 = 0; g2 < 2; ++g2) {
            const int g = w * 2 + g2;
            const int base = hoff + g * 128 + col * 16 + rr;
            if (base      < limit) atomicAdd(gbase + base,      tanh_fast(d0[g2]));
            if (base + 16 < limit) atomicAdd(gbase + base + 16, tanh_fast(d1[g2]));
            if (base + 8  < limit) atomicAdd(gbase + base + 8,  tanh_fast(d2[g2]));
            if (base + 24 < limit) atomicAdd(gbase + base + 24, tanh_fast(d3[g2]));
        }
    }
}

// ---------------------------------------------------------------------------
// Launch: memset(out) + tiny prep -> synth (same stream, graph-capturable;
// cudaMemsetAsync becomes a memset node in the captured graph)
// ---------------------------------------------------------------------------
extern "C" void kernel_launch(void* const* d_in, const int* in_sizes, int n_in,
                              void* d_out, int out_size) {
    const float* freq     = (const float*)d_in[0];
    const float* velocity = (const float*)d_in[1];
    const float* w1       = (const float*)d_in[2];
    const float* b1       = (const float*)d_in[3];
    const float* w2       = (const float*)d_in[4];
    const float* b2       = (const float*)d_in[5];
    const float* ws1      = (const float*)d_in[6];
    const float* bs1      = (const float*)d_in[7];
    const float* ws2      = (const float*)d_in[8];
    const float* bs2      = (const float*)d_in[9];
    const float* fir      = (const float*)d_in[10];
    const int*   starts   = (const int*)d_in[11];
    const int*   lengths  = (const int*)d_in[12];
    float* out = (float*)d_out;
    const int D = out_size;                  // duration_samples == out_size

    cudaMemsetAsync(out, 0, (size_t)D * sizeof(float), 0);
    prep_kernel<<<4, NTHREADS>>>(freq, velocity, w1, b1, w2, b2,
                                 ws1, bs1, ws2, bs2, fir,
                                 starts, lengths, D);
    dim3 grid(LL / TILE, NN);                // 8 x 1024 blocks, early-exit culls
    synth_kernel<<<grid, NTHREADS>>>(freq, starts, out);
}